// round 2
// baseline (speedup 1.0000x reference)
#include <cuda_runtime.h>
#include <cstdint>

#define N_NODES 50000
#define MAX_E   800000

// ---------------- device scratch (allocation-free rule: static globals) ----
__device__ float g_Q[N_NODES * 128];
__device__ float g_K[N_NODES * 128];
__device__ float g_V[N_NODES * 128];
__device__ float g_ssum[N_NODES * 8];
__device__ float g_P[256];   // softmax(S): [4][64]

// ---------------- zero out + ssum -----------------------------------------
__global__ void zero_kernel(float4* __restrict__ out, int N) {
    int i = blockIdx.x * blockDim.x + threadIdx.x;
    int n4 = N * 32;                       // N*128 floats / 4
    if (i < n4) out[i] = make_float4(0.f, 0.f, 0.f, 0.f);
    if (i < N * 8) g_ssum[i] = 0.f;
}

// ---------------- P = softmax(S, axis=1), S: [4][64] ----------------------
__global__ void softmaxS_kernel(const float* __restrict__ S) {
    int t = threadIdx.x;                   // 256 threads
    int a = t >> 6;                        // row 0..3
    int c = t & 63;                        // col 0..63
    float v = __expf(S[a * 64 + c]);
    float s = v;
    #pragma unroll
    for (int o = 16; o; o >>= 1) s += __shfl_xor_sync(0xffffffffu, s, o);
    __shared__ float part[8];
    if ((t & 31) == 0) part[t >> 5] = s;
    __syncthreads();
    float sum = part[a * 2] + part[a * 2 + 1];
    g_P[a * 64 + c] = v / sum;
}

// ---------------- QKV GEMM: out = x @ W + b (3 weight phases) -------------
// BM=64 nodes, BN=128 cols, BK=32. 256 threads, micro-tile 4 rows x 8 cols.
#define BM 64
#define BN 128
#define BK 32

__global__ __launch_bounds__(256) void qkv_kernel(
    const float* __restrict__ x,
    const float* __restrict__ Wq, const float* __restrict__ bq,
    const float* __restrict__ Wk, const float* __restrict__ bk,
    const float* __restrict__ Wv, const float* __restrict__ bv,
    int N)
{
    __shared__ float xs[BM][36];           // padded: float4-aligned stride
    __shared__ float ws[BK][132];

    int tid = threadIdx.x;
    int ty = tid >> 4;                     // 0..15 -> rows ty*4 .. ty*4+3
    int tx = tid & 15;                     // 0..15 -> cols tx*8 .. tx*8+7
    int ty4 = ty * 4;
    int tx8 = tx * 8;
    int row0 = blockIdx.x * BM;

    for (int ph = 0; ph < 3; ++ph) {
        const float* W    = (ph == 0) ? Wq : (ph == 1) ? Wk : Wv;
        const float* bias = (ph == 0) ? bq : (ph == 1) ? bk : bv;
        float*       optr = (ph == 0) ? g_Q : (ph == 1) ? g_K : g_V;

        float acc[4][8];
        #pragma unroll
        for (int r = 0; r < 4; ++r)
            #pragma unroll
            for (int c = 0; c < 8; ++c) acc[r][c] = 0.f;

        for (int kt = 0; kt < 128; kt += BK) {
            // load x tile: 64x32 floats = 512 float4, 2 per thread
            #pragma unroll
            for (int j = 0; j < 2; ++j) {
                int i4 = tid + 256 * j;
                int r  = i4 >> 3;
                int c4 = i4 & 7;
                int gr = row0 + r;
                float4 v = make_float4(0.f, 0.f, 0.f, 0.f);
                if (gr < N)
                    v = *reinterpret_cast<const float4*>(&x[gr * 128 + kt + c4 * 4]);
                *reinterpret_cast<float4*>(&xs[r][c4 * 4]) = v;
            }
            // load W tile: 32x128 floats = 1024 float4, 4 per thread
            #pragma unroll
            for (int j = 0; j < 4; ++j) {
                int i4 = tid + 256 * j;
                int kk = i4 >> 5;
                int c4 = i4 & 31;
                float4 v = *reinterpret_cast<const float4*>(&W[(kt + kk) * 128 + c4 * 4]);
                *reinterpret_cast<float4*>(&ws[kk][c4 * 4]) = v;
            }
            __syncthreads();

            #pragma unroll 8
            for (int kk = 0; kk < BK; ++kk) {
                float a0 = xs[ty4 + 0][kk];
                float a1 = xs[ty4 + 1][kk];
                float a2 = xs[ty4 + 2][kk];
                float a3 = xs[ty4 + 3][kk];
                float b[8];
                #pragma unroll
                for (int c = 0; c < 8; ++c) b[c] = ws[kk][tx8 + c];
                #pragma unroll
                for (int c = 0; c < 8; ++c) {
                    acc[0][c] += a0 * b[c];
                    acc[1][c] += a1 * b[c];
                    acc[2][c] += a2 * b[c];
                    acc[3][c] += a3 * b[c];
                }
            }
            __syncthreads();
        }

        float bb[8];
        #pragma unroll
        for (int c = 0; c < 8; ++c) bb[c] = bias[tx8 + c];

        #pragma unroll
        for (int r = 0; r < 4; ++r) {
            int gr = row0 + ty4 + r;
            if (gr < N) {
                float4 v0 = make_float4(acc[r][0] + bb[0], acc[r][1] + bb[1],
                                        acc[r][2] + bb[2], acc[r][3] + bb[3]);
                float4 v1 = make_float4(acc[r][4] + bb[4], acc[r][5] + bb[5],
                                        acc[r][6] + bb[6], acc[r][7] + bb[7]);
                *reinterpret_cast<float4*>(&optr[gr * 128 + tx8])     = v0;
                *reinterpret_cast<float4*>(&optr[gr * 128 + tx8 + 4]) = v1;
            }
        }
        __syncthreads();   // protect smem reuse across phases
    }
}

// ---------------- per-node RoPE rotation of Q and K (in place) ------------
// warp per node; lane l owns flat elements 4l..4l+3.
__global__ __launch_bounds__(256) void rot_kernel(const float* __restrict__ ang, int N) {
    int w    = (blockIdx.x * blockDim.x + threadIdx.x) >> 5;
    int lane = threadIdx.x & 31;
    if (w >= N) return;
    int n = w;

    float a0 = ang[n * 4 + 0], a1 = ang[n * 4 + 1];
    float a2 = ang[n * 4 + 2], a3 = ang[n * 4 + 3];

    int m0 = 2 * lane, m1 = 2 * lane + 1;
    float t0 = a0 * g_P[m0] + a1 * g_P[64 + m0] + a2 * g_P[128 + m0] + a3 * g_P[192 + m0];
    float t1 = a0 * g_P[m1] + a1 * g_P[64 + m1] + a2 * g_P[128 + m1] + a3 * g_P[192 + m1];
    float c0, s0, c1, s1;
    __sincosf(t0, &s0, &c0);
    __sincosf(t1, &s1, &c1);

    float4 q = reinterpret_cast<const float4*>(g_Q)[n * 32 + lane];
    float4 k = reinterpret_cast<const float4*>(g_K)[n * 32 + lane];

    // partner (rot2) values, sign folded in
    float qp[4], kp[4];
    int j0 = 4 * lane;
    #pragma unroll
    for (int i = 0; i < 4; ++i) {
        int j  = j0 + i;
        int h  = j >> 4;
        int jj = j & 15;
        int pidx; float sg;
        if (jj < 8) { pidx = (h << 4) + 2 * jj + 1;  sg = -1.f; }
        else        { pidx = (h << 4) + 2 * jj - 16; sg =  1.f; }
        qp[i] = g_Q[n * 128 + pidx] * sg;
        kp[i] = g_K[n * 128 + pidx] * sg;
    }
    __syncwarp();   // all loads done before any in-place store (intra-warp hazard)

    float4 qo, ko;
    qo.x = q.x * c0 + qp[0] * s0;  ko.x = k.x * c0 + kp[0] * s0;
    qo.y = q.y * c0 + qp[1] * s0;  ko.y = k.y * c0 + kp[1] * s0;
    qo.z = q.z * c1 + qp[2] * s1;  ko.z = k.z * c1 + kp[2] * s1;
    qo.w = q.w * c1 + qp[3] * s1;  ko.w = k.w * c1 + kp[3] * s1;

    reinterpret_cast<float4*>(g_Q)[n * 32 + lane] = qo;
    reinterpret_cast<float4*>(g_K)[n * 32 + lane] = ko;
}

// ---------------- edge pass: scores + exp + scatter-add -------------------
// warp per edge. Accumulates exp-weights into g_ssum and w*V into out.
__global__ __launch_bounds__(256) void edge_kernel(
    const int* __restrict__ ei, int E, float* __restrict__ out)
{
    int w    = (blockIdx.x * blockDim.x + threadIdx.x) >> 5;
    int lane = threadIdx.x & 31;
    if (w >= E) return;

    int src = ei[w];
    int dst = ei[E + w];

    float4 k4 = reinterpret_cast<const float4*>(g_K)[src * 32 + lane];
    float4 q4 = reinterpret_cast<const float4*>(g_Q)[dst * 32 + lane];
    float p = k4.x * q4.x + k4.y * q4.y + k4.z * q4.z + k4.w * q4.w;
    p += __shfl_xor_sync(0xffffffffu, p, 1);
    p += __shfl_xor_sync(0xffffffffu, p, 2);   // all 4 lanes of head group hold sum

    float s   = fminf(fmaxf(p * 0.25f, -5.f), 5.f);
    float wgt = __expf(s);

    // gather 4 head-weights into lanes 0 and 16, one v4 red each
    float w1 = __shfl_sync(0xffffffffu, wgt, lane | 4);
    float w2 = __shfl_sync(0xffffffffu, wgt, lane | 8);
    float w3 = __shfl_sync(0xffffffffu, wgt, lane | 12);
    if ((lane & 15) == 0) {
        float* sp = g_ssum + dst * 8 + (lane >> 2);
        asm volatile("red.global.add.v4.f32 [%0], {%1,%2,%3,%4};"
                     :: "l"(sp), "f"(wgt), "f"(w1), "f"(w2), "f"(w3) : "memory");
    }

    float4 v4 = reinterpret_cast<const float4*>(g_V)[src * 32 + lane];
    float* op = out + (size_t)dst * 128 + lane * 4;
    asm volatile("red.global.add.v4.f32 [%0], {%1,%2,%3,%4};"
                 :: "l"(op), "f"(v4.x * wgt), "f"(v4.y * wgt),
                    "f"(v4.z * wgt), "f"(v4.w * wgt) : "memory");
}

// ---------------- normalize: out /= (ssum + 1e-16) ------------------------
__global__ void norm_kernel(float4* __restrict__ out, int N) {
    int i = blockIdx.x * blockDim.x + threadIdx.x;   // over N*32 float4s
    if (i >= N * 32) return;
    float ss  = g_ssum[i >> 2];                      // (i*4)>>4
    float inv = 1.f / (ss + 1e-16f);
    float4 v = out[i];
    v.x *= inv; v.y *= inv; v.z *= inv; v.w *= inv;
    out[i] = v;
}

// ---------------- launch ---------------------------------------------------
extern "C" void kernel_launch(void* const* d_in, const int* in_sizes, int n_in,
                              void* d_out, int out_size)
{
    const float* x   = (const float*)d_in[0];
    const float* ang = (const float*)d_in[1];
    const int*   ei  = (const int*)  d_in[2];
    const float* Wq  = (const float*)d_in[3];
    const float* bq  = (const float*)d_in[4];
    const float* Wk  = (const float*)d_in[5];
    const float* bk  = (const float*)d_in[6];
    const float* Wv  = (const float*)d_in[7];
    const float* bv  = (const float*)d_in[8];
    const float* S   = (const float*)d_in[9];
    float* out = (float*)d_out;

    int N = in_sizes[0] / 128;
    int E = in_sizes[2] / 2;

    zero_kernel<<<(N * 32 + 255) / 256, 256>>>((float4*)out, N);
    softmaxS_kernel<<<1, 256>>>(S);
    qkv_kernel<<<(N + BM - 1) / BM, 256>>>(x, Wq, bq, Wk, bk, Wv, bv, N);
    rot_kernel<<<(N + 7) / 8, 256>>>(ang, N);
    edge_kernel<<<(E + 7) / 8, 256>>>(ei, E, out);
    norm_kernel<<<(N * 32 + 255) / 256, 256>>>((float4*)out, N);
}

// round 4
// speedup vs baseline: 1.5096x; 1.5096x over previous
#include <cuda_runtime.h>
#include <cuda_bf16.h>
#include <cstdint>

#define N_NODES 50000

// ---------------- device scratch ------------------------------------------
__device__ float g_Q[N_NODES * 128];
__device__ float g_K[N_NODES * 128];
__device__ float g_V[N_NODES * 128];
__device__ float g_ssum[N_NODES * 8];
__device__ float g_P[256];                       // softmax(S): [4][64]
__device__ __nv_bfloat16 g_Whi[3 * 16384];       // W^T [n][k] row-major, bf16 hi
__device__ __nv_bfloat16 g_Wlo[3 * 16384];       // bf16 residual

// ---------------- helpers --------------------------------------------------
__device__ __forceinline__ uint32_t smem_u32(const void* p) {
    uint32_t a;
    asm("{ .reg .u64 t; cvta.to.shared.u64 t, %1; cvt.u32.u64 %0, t; }" : "=r"(a) : "l"(p));
    return a;
}
__device__ __forceinline__ void ldm_x4(uint32_t* r, uint32_t addr) {
    asm volatile("ldmatrix.sync.aligned.m8n8.x4.shared.b16 {%0,%1,%2,%3}, [%4];"
                 : "=r"(r[0]), "=r"(r[1]), "=r"(r[2]), "=r"(r[3]) : "r"(addr));
}
__device__ __forceinline__ void mma16816(float* d, const uint32_t* a, const uint32_t* b) {
    asm volatile("mma.sync.aligned.m16n8k16.row.col.f32.bf16.bf16.f32 "
                 "{%0,%1,%2,%3}, {%4,%5,%6,%7}, {%8,%9}, {%0,%1,%2,%3};"
                 : "+f"(d[0]), "+f"(d[1]), "+f"(d[2]), "+f"(d[3])
                 : "r"(a[0]), "r"(a[1]), "r"(a[2]), "r"(a[3]), "r"(b[0]), "r"(b[1]));
}
__device__ __forceinline__ uint32_t pack_bf2(__nv_bfloat16 a, __nv_bfloat16 b) {
    return (uint32_t)__bfloat16_as_ushort(a) | ((uint32_t)__bfloat16_as_ushort(b) << 16);
}

// smem layout (bytes). x/W tiles: 128 rows x 136 bf16 (pitch 272B, 17x16B -> no conflicts)
#define XH_OFF  0
#define XL_OFF  34816
#define WH_OFF  69632
#define WL_OFF  104448
#define OUT_OFF 139264            // 128 x 132 f32 (pitch 528B)
#define QKV_SMEM (139264 + 128 * 132 * 4)   // 206848

// ---------------- zero out + ssum -----------------------------------------
__global__ void zero_kernel(float4* __restrict__ out, int N) {
    int i = blockIdx.x * blockDim.x + threadIdx.x;
    int n4 = N * 32;
    if (i < n4) out[i] = make_float4(0.f, 0.f, 0.f, 0.f);
    if (i < N * 8) g_ssum[i] = 0.f;
}

// ---------------- P = softmax(S, axis=1), S: [4][64] ----------------------
__global__ void softmaxS_kernel(const float* __restrict__ S) {
    int t = threadIdx.x;
    int a = t >> 6, c = t & 63;
    float v = __expf(S[a * 64 + c]);
    float s = v;
    #pragma unroll
    for (int o = 16; o; o >>= 1) s += __shfl_xor_sync(0xffffffffu, s, o);
    __shared__ float part[8];
    if ((t & 31) == 0) part[t >> 5] = s;
    __syncthreads();
    float sum = part[a * 2] + part[a * 2 + 1];
    g_P[a * 64 + c] = v / sum;
}

// ---------------- W[k][n] -> W^T[n][k] bf16 hi/lo --------------------------
__global__ void wconv_kernel(const float* __restrict__ Wq,
                             const float* __restrict__ Wk,
                             const float* __restrict__ Wv) {
    int i = blockIdx.x * blockDim.x + threadIdx.x;
    if (i >= 3 * 16384) return;
    int ph = i >> 14, rem = i & 16383;
    int k = rem >> 7, n = rem & 127;                 // read coalesced in n
    const float* W = (ph == 0) ? Wq : (ph == 1) ? Wk : Wv;
    float v = W[k * 128 + n];
    __nv_bfloat16 hi = __float2bfloat16_rn(v);
    __nv_bfloat16 lo = __float2bfloat16_rn(v - __bfloat162float(hi));
    g_Whi[ph * 16384 + n * 128 + k] = hi;
    g_Wlo[ph * 16384 + n * 128 + k] = lo;
}

// ---------------- fused QKV GEMM (mma.sync bf16 split) + bias + RoPE ------
__global__ __launch_bounds__(256, 1) void qkv_mma_kernel(
    const float* __restrict__ x, const float* __restrict__ ang,
    const float* __restrict__ bq, const float* __restrict__ bk,
    const float* __restrict__ bv, int N)
{
    extern __shared__ char smem[];
    uint32_t sb = smem_u32(smem);
    int tid = threadIdx.x, wid = tid >> 5, lane = tid & 31;
    int row0 = blockIdx.x * 128;

    // ---- stage x tile [128][128] -> bf16 hi/lo in padded smem ----
    #pragma unroll
    for (int j = 0; j < 16; ++j) {
        int idx  = tid + 256 * j;                 // 4096 float4s
        int row  = idx >> 5;
        int col0 = (idx & 31) * 4;
        int gr   = row0 + row;
        float4 v = make_float4(0.f, 0.f, 0.f, 0.f);
        if (gr < N) v = *reinterpret_cast<const float4*>(&x[(size_t)gr * 128 + col0]);
        __nv_bfloat16 h0 = __float2bfloat16_rn(v.x), h1 = __float2bfloat16_rn(v.y);
        __nv_bfloat16 h2 = __float2bfloat16_rn(v.z), h3 = __float2bfloat16_rn(v.w);
        __nv_bfloat16 l0 = __float2bfloat16_rn(v.x - __bfloat162float(h0));
        __nv_bfloat16 l1 = __float2bfloat16_rn(v.y - __bfloat162float(h1));
        __nv_bfloat16 l2 = __float2bfloat16_rn(v.z - __bfloat162float(h2));
        __nv_bfloat16 l3 = __float2bfloat16_rn(v.w - __bfloat162float(h3));
        uint32_t off = (uint32_t)row * 272u + (uint32_t)col0 * 2u;
        *reinterpret_cast<uint2*>(smem + XH_OFF + off) = make_uint2(pack_bf2(h0, h1), pack_bf2(h2, h3));
        *reinterpret_cast<uint2*>(smem + XL_OFF + off) = make_uint2(pack_bf2(l0, l1), pack_bf2(l2, l3));
    }

    int wm = wid & 3;        // warp row tile: rows wm*32 .. +31
    int wn = wid >> 2;       // warp col tile: cols wn*64 .. +63
    float* outs = reinterpret_cast<float*>(smem + OUT_OFF);

    for (int ph = 0; ph < 3; ++ph) {
        // ---- stage W^T hi/lo into padded smem ----
        {
            const uint4* sh = reinterpret_cast<const uint4*>(g_Whi + ph * 16384);
            const uint4* sl = reinterpret_cast<const uint4*>(g_Wlo + ph * 16384);
            #pragma unroll
            for (int j = 0; j < 8; ++j) {
                int c  = tid + 256 * j;           // 2048 16B chunks
                int n  = c >> 4;
                int ko = c & 15;
                uint32_t off = (uint32_t)n * 272u + (uint32_t)ko * 16u;
                *reinterpret_cast<uint4*>(smem + WH_OFF + off) = sh[c];
                *reinterpret_cast<uint4*>(smem + WL_OFF + off) = sl[c];
            }
        }
        __syncthreads();

        // ---- MMA mainloop ----
        float d[2][8][4];
        #pragma unroll
        for (int mi = 0; mi < 2; ++mi)
            #pragma unroll
            for (int nj = 0; nj < 8; ++nj)
                #pragma unroll
                for (int q = 0; q < 4; ++q) d[mi][nj][q] = 0.f;

        #pragma unroll
        for (int kk = 0; kk < 8; ++kk) {
            uint32_t axh[2][4], axl[2][4];
            #pragma unroll
            for (int mi = 0; mi < 2; ++mi) {
                int r = wm * 32 + mi * 16 + (lane & 15);
                int c = kk * 16 + (lane >> 4) * 8;
                uint32_t a = sb + XH_OFF + (uint32_t)r * 272u + (uint32_t)c * 2u;
                ldm_x4(axh[mi], a);
                ldm_x4(axl[mi], a + (XL_OFF - XH_OFF));
            }
            uint32_t bwh[8][2], bwl[8][2];
            #pragma unroll
            for (int p2 = 0; p2 < 4; ++p2) {      // pairs of n8 tiles
                int nr = wn * 64 + p2 * 16 + ((lane >> 4) & 1) * 8 + (lane & 7);
                int c  = kk * 16 + ((lane >> 3) & 1) * 8;
                uint32_t a = sb + WH_OFF + (uint32_t)nr * 272u + (uint32_t)c * 2u;
                uint32_t rh[4], rl[4];
                ldm_x4(rh, a);
                ldm_x4(rl, a + (WL_OFF - WH_OFF));
                bwh[p2 * 2][0] = rh[0]; bwh[p2 * 2][1] = rh[1];
                bwh[p2 * 2 + 1][0] = rh[2]; bwh[p2 * 2 + 1][1] = rh[3];
                bwl[p2 * 2][0] = rl[0]; bwl[p2 * 2][1] = rl[1];
                bwl[p2 * 2 + 1][0] = rl[2]; bwl[p2 * 2 + 1][1] = rl[3];
            }
            #pragma unroll
            for (int mi = 0; mi < 2; ++mi)
                #pragma unroll
                for (int nj = 0; nj < 8; ++nj) {
                    mma16816(d[mi][nj], axh[mi], bwh[nj]);
                    mma16816(d[mi][nj], axh[mi], bwl[nj]);
                    mma16816(d[mi][nj], axl[mi], bwh[nj]);
                }
        }

        // ---- store D frags to OUT smem ----
        #pragma unroll
        for (int mi = 0; mi < 2; ++mi)
            #pragma unroll
            for (int nj = 0; nj < 8; ++nj) {
                int r = wm * 32 + mi * 16 + (lane >> 2);
                int c = wn * 64 + nj * 8 + 2 * (lane & 3);
                *reinterpret_cast<float2*>(&outs[r * 132 + c]) =
                    make_float2(d[mi][nj][0], d[mi][nj][1]);
                *reinterpret_cast<float2*>(&outs[(r + 8) * 132 + c]) =
                    make_float2(d[mi][nj][2], d[mi][nj][3]);
            }
        __syncthreads();

        // ---- epilogue: bias + (RoPE for Q,K) + store to global ----
        {
            const float* bias = (ph == 0) ? bq : (ph == 1) ? bk : bv;
            float* gout = (ph == 0) ? g_Q : (ph == 1) ? g_K : g_V;
            #pragma unroll
            for (int rr = 0; rr < 16; ++rr) {
                int row = wid * 16 + rr;
                int n = row0 + row;
                if (n >= N) break;
                int j0 = lane * 4;
                const float* orow = &outs[row * 132];
                float v0 = orow[j0 + 0] + bias[j0 + 0];
                float v1 = orow[j0 + 1] + bias[j0 + 1];
                float v2 = orow[j0 + 2] + bias[j0 + 2];
                float v3 = orow[j0 + 3] + bias[j0 + 3];
                float4 ov;
                if (ph < 2) {
                    float a0 = ang[n * 4 + 0], a1 = ang[n * 4 + 1];
                    float a2 = ang[n * 4 + 2], a3 = ang[n * 4 + 3];
                    int m0 = 2 * lane, m1 = 2 * lane + 1;
                    float t0 = a0 * g_P[m0] + a1 * g_P[64 + m0] + a2 * g_P[128 + m0] + a3 * g_P[192 + m0];
                    float t1 = a0 * g_P[m1] + a1 * g_P[64 + m1] + a2 * g_P[128 + m1] + a3 * g_P[192 + m1];
                    float c0, s0, c1, s1;
                    __sincosf(t0, &s0, &c0);
                    __sincosf(t1, &s1, &c1);
                    float pv[4];
                    #pragma unroll
                    for (int i = 0; i < 4; ++i) {
                        int j = j0 + i;
                        int jj = j & 15, hb = j & 0x70;
                        int p; float sg;
                        if (jj < 8) { p = hb + 2 * jj + 1;  sg = -1.f; }
                        else        { p = hb + 2 * jj - 16; sg =  1.f; }
                        pv[i] = sg * (orow[p] + bias[p]);
                    }
                    ov.x = v0 * c0 + pv[0] * s0;
                    ov.y = v1 * c0 + pv[1] * s0;
                    ov.z = v2 * c1 + pv[2] * s1;
                    ov.w = v3 * c1 + pv[3] * s1;
                } else {
                    ov = make_float4(v0, v1, v2, v3);
                }
                *reinterpret_cast<float4*>(&gout[(size_t)n * 128 + j0]) = ov;
            }
        }
        __syncthreads();   // OUT / W smem safe to reuse next phase
    }
}

// ---------------- edge pass: scores + exp + scatter-add -------------------
__global__ __launch_bounds__(256) void edge_kernel(
    const int* __restrict__ ei, int E, float* __restrict__ out)
{
    int w    = (blockIdx.x * blockDim.x + threadIdx.x) >> 5;
    int lane = threadIdx.x & 31;
    if (w >= E) return;

    int src = ei[w];
    int dst = ei[E + w];

    float4 k4 = reinterpret_cast<const float4*>(g_K)[src * 32 + lane];
    float4 q4 = reinterpret_cast<const float4*>(g_Q)[dst * 32 + lane];
    float p = k4.x * q4.x + k4.y * q4.y + k4.z * q4.z + k4.w * q4.w;
    p += __shfl_xor_sync(0xffffffffu, p, 1);
    p += __shfl_xor_sync(0xffffffffu, p, 2);

    float s   = fminf(fmaxf(p * 0.25f, -5.f), 5.f);
    float wgt = __expf(s);

    float w1 = __shfl_sync(0xffffffffu, wgt, lane | 4);
    float w2 = __shfl_sync(0xffffffffu, wgt, lane | 8);
    float w3 = __shfl_sync(0xffffffffu, wgt, lane | 12);
    if ((lane & 15) == 0) {
        float* sp = g_ssum + dst * 8 + (lane >> 2);
        asm volatile("red.global.add.v4.f32 [%0], {%1,%2,%3,%4};"
                     :: "l"(sp), "f"(wgt), "f"(w1), "f"(w2), "f"(w3) : "memory");
    }

    float4 v4 = reinterpret_cast<const float4*>(g_V)[src * 32 + lane];
    float* op = out + (size_t)dst * 128 + lane * 4;
    asm volatile("red.global.add.v4.f32 [%0], {%1,%2,%3,%4};"
                 :: "l"(op), "f"(v4.x * wgt), "f"(v4.y * wgt),
                    "f"(v4.z * wgt), "f"(v4.w * wgt) : "memory");
}

// ---------------- normalize: out /= (ssum + 1e-16) ------------------------
__global__ void norm_kernel(float4* __restrict__ out, int N) {
    int i = blockIdx.x * blockDim.x + threadIdx.x;
    if (i >= N * 32) return;
    float ss  = g_ssum[i >> 2];
    float inv = 1.f / (ss + 1e-16f);
    float4 v = out[i];
    v.x *= inv; v.y *= inv; v.z *= inv; v.w *= inv;
    out[i] = v;
}

// ---------------- launch ---------------------------------------------------
extern "C" void kernel_launch(void* const* d_in, const int* in_sizes, int n_in,
                              void* d_out, int out_size)
{
    const float* x   = (const float*)d_in[0];
    const float* ang = (const float*)d_in[1];
    const int*   ei  = (const int*)  d_in[2];
    const float* Wq  = (const float*)d_in[3];
    const float* bq  = (const float*)d_in[4];
    const float* Wk  = (const float*)d_in[5];
    const float* bk  = (const float*)d_in[6];
    const float* Wv  = (const float*)d_in[7];
    const float* bv  = (const float*)d_in[8];
    const float* S   = (const float*)d_in[9];
    float* out = (float*)d_out;

    int N = in_sizes[0] / 128;
    int E = in_sizes[2] / 2;

    cudaFuncSetAttribute(qkv_mma_kernel,
                         cudaFuncAttributeMaxDynamicSharedMemorySize, QKV_SMEM);

    zero_kernel<<<(N * 32 + 255) / 256, 256>>>((float4*)out, N);
    softmaxS_kernel<<<1, 256>>>(S);
    wconv_kernel<<<(3 * 16384 + 255) / 256, 256>>>(Wq, Wk, Wv);
    qkv_mma_kernel<<<(N + 127) / 128, 256, QKV_SMEM>>>(x, ang, bq, bk, bv, N);
    edge_kernel<<<(E + 7) / 8, 256>>>(ei, E, out);
    norm_kernel<<<(N * 32 + 255) / 256, 256>>>((float4*)out, N);
}

// round 5
// speedup vs baseline: 1.6044x; 1.0629x over previous
#include <cuda_runtime.h>
#include <cuda_bf16.h>
#include <cstdint>

#define N_NODES 50000

// ---------------- device scratch ------------------------------------------
__device__ float g_Q[N_NODES * 128];
__device__ float g_K[N_NODES * 128];
__device__ float g_V[N_NODES * 128];
__device__ float g_ssum[N_NODES * 8];
__device__ float g_P[256];                         // softmax(S): [4][64]
// W packed in mma b-frag order: [ph][kt:8][nt:16][lane:32][8 bf16: hi w0b0,w0b1,w1b0,w1b1, lo ...]
__device__ __nv_bfloat16 g_Wf[3 * 8 * 16 * 32 * 8];

// ---------------- helpers --------------------------------------------------
__device__ __forceinline__ uint32_t smem_u32(const void* p) {
    uint32_t a;
    asm("{ .reg .u64 t; cvta.to.shared.u64 t, %1; cvt.u32.u64 %0, t; }" : "=r"(a) : "l"(p));
    return a;
}
__device__ __forceinline__ void ldm_x4(uint32_t* r, uint32_t addr) {
    asm volatile("ldmatrix.sync.aligned.m8n8.x4.shared.b16 {%0,%1,%2,%3}, [%4];"
                 : "=r"(r[0]), "=r"(r[1]), "=r"(r[2]), "=r"(r[3]) : "r"(addr));
}
__device__ __forceinline__ void mma16816(float* d, const uint32_t* a, uint32_t b0, uint32_t b1) {
    asm volatile("mma.sync.aligned.m16n8k16.row.col.f32.bf16.bf16.f32 "
                 "{%0,%1,%2,%3}, {%4,%5,%6,%7}, {%8,%9}, {%0,%1,%2,%3};"
                 : "+f"(d[0]), "+f"(d[1]), "+f"(d[2]), "+f"(d[3])
                 : "r"(a[0]), "r"(a[1]), "r"(a[2]), "r"(a[3]), "r"(b0), "r"(b1));
}
__device__ __forceinline__ uint32_t pack_bf2(__nv_bfloat16 a, __nv_bfloat16 b) {
    return (uint32_t)__bfloat16_as_ushort(a) | ((uint32_t)__bfloat16_as_ushort(b) << 16);
}

// smem layout (bytes). x tiles: 64 rows x 136 bf16 (pitch 272B)
#define XH_OFF  0
#define XL_OFF  17408
#define OUT_OFF 34816                 // 64 x 132 f32
#define QKV_SMEM (34816 + 64 * 132 * 4)   // 68608

// ---------------- zero out + ssum -----------------------------------------
__global__ void zero_kernel(float4* __restrict__ out, int N) {
    int i = blockIdx.x * blockDim.x + threadIdx.x;
    int n4 = N * 32;
    if (i < n4) out[i] = make_float4(0.f, 0.f, 0.f, 0.f);
    if (i < N * 8) g_ssum[i] = 0.f;
}

// ---------------- P = softmax(S, axis=1), S: [4][64] ----------------------
__global__ void softmaxS_kernel(const float* __restrict__ S) {
    int t = threadIdx.x;
    int a = t >> 6, c = t & 63;
    float v = __expf(S[a * 64 + c]);
    float s = v;
    #pragma unroll
    for (int o = 16; o; o >>= 1) s += __shfl_xor_sync(0xffffffffu, s, o);
    __shared__ float part[8];
    if ((t & 31) == 0) part[t >> 5] = s;
    __syncthreads();
    float sum = part[a * 2] + part[a * 2 + 1];
    g_P[a * 64 + c] = v / sum;
}

// ---------------- W[k][n] -> packed mma b-frags (bf16 hi/lo) --------------
// b-frag (m16n8k16, col-major B): thread t: n = nt*8 + (t>>2), k word0 = kt*16 + (t&3)*2,
// word1 = word0 + 8. Each lane block: 16B = [hi w0, hi w1, lo w0, lo w1].
__global__ void wconv_kernel(const float* __restrict__ Wq,
                             const float* __restrict__ Wk,
                             const float* __restrict__ Wv) {
    int i = blockIdx.x * blockDim.x + threadIdx.x;
    if (i >= 3 * 16384) return;
    int ph = i >> 14, rem = i & 16383;
    int k = rem >> 7, n = rem & 127;                 // coalesced read in n
    const float* W = (ph == 0) ? Wq : (ph == 1) ? Wk : Wv;
    float v = W[k * 128 + n];
    __nv_bfloat16 hi = __float2bfloat16_rn(v);
    __nv_bfloat16 lo = __float2bfloat16_rn(v - __bfloat162float(hi));
    int kt = k >> 4, nt = n >> 3;
    int t  = ((n & 7) << 2) | ((k & 7) >> 1);
    int word = (k >> 3) & 1, half = k & 1;
    size_t base = ((size_t)((ph * 8 + kt) * 16 + nt) * 32 + t) * 8;
    g_Wf[base + word * 2 + half]     = hi;
    g_Wf[base + 4 + word * 2 + half] = lo;
}

// ---------------- fused QKV GEMM (mma.sync bf16 split) + bias + RoPE ------
__global__ __launch_bounds__(256, 2) void qkv_mma_kernel(
    const float* __restrict__ x, const float* __restrict__ ang,
    const float* __restrict__ bq, const float* __restrict__ bk,
    const float* __restrict__ bv, int N)
{
    extern __shared__ char smem[];
    uint32_t sb = smem_u32(smem);
    int tid = threadIdx.x, wid = tid >> 5, lane = tid & 31;
    int row0 = blockIdx.x * 64;

    // ---- stage x tile [64][128] -> bf16 hi/lo in padded smem ----
    #pragma unroll
    for (int j = 0; j < 8; ++j) {
        int idx  = tid + 256 * j;                 // 2048 float4s
        int row  = idx >> 5;
        int col0 = (idx & 31) * 4;
        int gr   = row0 + row;
        float4 v = make_float4(0.f, 0.f, 0.f, 0.f);
        if (gr < N) v = *reinterpret_cast<const float4*>(&x[(size_t)gr * 128 + col0]);
        __nv_bfloat16 h0 = __float2bfloat16_rn(v.x), h1 = __float2bfloat16_rn(v.y);
        __nv_bfloat16 h2 = __float2bfloat16_rn(v.z), h3 = __float2bfloat16_rn(v.w);
        __nv_bfloat16 l0 = __float2bfloat16_rn(v.x - __bfloat162float(h0));
        __nv_bfloat16 l1 = __float2bfloat16_rn(v.y - __bfloat162float(h1));
        __nv_bfloat16 l2 = __float2bfloat16_rn(v.z - __bfloat162float(h2));
        __nv_bfloat16 l3 = __float2bfloat16_rn(v.w - __bfloat162float(h3));
        uint32_t off = (uint32_t)row * 272u + (uint32_t)col0 * 2u;
        *reinterpret_cast<uint2*>(smem + XH_OFF + off) = make_uint2(pack_bf2(h0, h1), pack_bf2(h2, h3));
        *reinterpret_cast<uint2*>(smem + XL_OFF + off) = make_uint2(pack_bf2(l0, l1), pack_bf2(l2, l3));
    }
    __syncthreads();

    int wm = wid & 3;        // rows wm*16 .. +15
    int wn = wid >> 2;       // cols wn*64 .. +63
    float* outs = reinterpret_cast<float*>(smem + OUT_OFF);

    for (int ph = 0; ph < 3; ++ph) {
        float d[8][4];
        #pragma unroll
        for (int nj = 0; nj < 8; ++nj)
            #pragma unroll
            for (int q = 0; q < 4; ++q) d[nj][q] = 0.f;

        const uint4* wf = reinterpret_cast<const uint4*>(g_Wf) + ((size_t)ph * 8 * 16 + wn * 8) * 32 + lane;

        #pragma unroll 2
        for (int kk = 0; kk < 8; ++kk) {
            uint32_t ah[4], al[4];
            {
                int r = wm * 16 + (lane & 15);
                int c = kk * 16 + (lane >> 4) * 8;
                uint32_t a = sb + XH_OFF + (uint32_t)r * 272u + (uint32_t)c * 2u;
                ldm_x4(ah, a);
                ldm_x4(al, a + (XL_OFF - XH_OFF));
            }
            uint4 bfr[8];
            #pragma unroll
            for (int nj = 0; nj < 8; ++nj)
                bfr[nj] = wf[((size_t)kk * 16 + nj) * 32];
            #pragma unroll
            for (int nj = 0; nj < 8; ++nj) {
                mma16816(d[nj], ah, bfr[nj].x, bfr[nj].y);
                mma16816(d[nj], ah, bfr[nj].z, bfr[nj].w);
                mma16816(d[nj], al, bfr[nj].x, bfr[nj].y);
            }
        }

        // ---- store D frags to OUT smem ----
        #pragma unroll
        for (int nj = 0; nj < 8; ++nj) {
            int r = wm * 16 + (lane >> 2);
            int c = wn * 64 + nj * 8 + 2 * (lane & 3);
            *reinterpret_cast<float2*>(&outs[r * 132 + c])       = make_float2(d[nj][0], d[nj][1]);
            *reinterpret_cast<float2*>(&outs[(r + 8) * 132 + c]) = make_float2(d[nj][2], d[nj][3]);
        }
        __syncthreads();

        // ---- epilogue: bias + (RoPE for Q,K) + store to global ----
        {
            const float* bias = (ph == 0) ? bq : (ph == 1) ? bk : bv;
            float* gout = (ph == 0) ? g_Q : (ph == 1) ? g_K : g_V;
            #pragma unroll
            for (int rr = 0; rr < 8; ++rr) {
                int row = wid * 8 + rr;
                int n = row0 + row;
                if (n >= N) break;
                int j0 = lane * 4;
                const float* orow = &outs[row * 132];
                float v0 = orow[j0 + 0] + bias[j0 + 0];
                float v1 = orow[j0 + 1] + bias[j0 + 1];
                float v2 = orow[j0 + 2] + bias[j0 + 2];
                float v3 = orow[j0 + 3] + bias[j0 + 3];
                float4 ov;
                if (ph < 2) {
                    float a0 = ang[n * 4 + 0], a1 = ang[n * 4 + 1];
                    float a2 = ang[n * 4 + 2], a3 = ang[n * 4 + 3];
                    int m0 = 2 * lane, m1 = 2 * lane + 1;
                    float t0 = a0 * g_P[m0] + a1 * g_P[64 + m0] + a2 * g_P[128 + m0] + a3 * g_P[192 + m0];
                    float t1 = a0 * g_P[m1] + a1 * g_P[64 + m1] + a2 * g_P[128 + m1] + a3 * g_P[192 + m1];
                    float c0, s0, c1, s1;
                    __sincosf(t0, &s0, &c0);
                    __sincosf(t1, &s1, &c1);
                    float pv[4];
                    #pragma unroll
                    for (int i = 0; i < 4; ++i) {
                        int j = j0 + i;
                        int jj = j & 15, hb = j & 0x70;
                        int p; float sg;
                        if (jj < 8) { p = hb + 2 * jj + 1;  sg = -1.f; }
                        else        { p = hb + 2 * jj - 16; sg =  1.f; }
                        pv[i] = sg * (orow[p] + bias[p]);
                    }
                    ov.x = v0 * c0 + pv[0] * s0;
                    ov.y = v1 * c0 + pv[1] * s0;
                    ov.z = v2 * c1 + pv[2] * s1;
                    ov.w = v3 * c1 + pv[3] * s1;
                } else {
                    ov = make_float4(v0, v1, v2, v3);
                }
                *reinterpret_cast<float4*>(&gout[(size_t)n * 128 + j0]) = ov;
            }
        }
        __syncthreads();   // OUT safe to reuse next phase
    }
}

// ---------------- edge pass: scores + exp + scatter-add -------------------
__global__ __launch_bounds__(256) void edge_kernel(
    const int* __restrict__ ei, int E, float* __restrict__ out)
{
    int w    = (blockIdx.x * blockDim.x + threadIdx.x) >> 5;
    int lane = threadIdx.x & 31;
    if (w >= E) return;

    int src = ei[w];
    int dst = ei[E + w];

    float4 k4 = reinterpret_cast<const float4*>(g_K)[src * 32 + lane];
    float4 q4 = reinterpret_cast<const float4*>(g_Q)[dst * 32 + lane];
    float p = k4.x * q4.x + k4.y * q4.y + k4.z * q4.z + k4.w * q4.w;
    p += __shfl_xor_sync(0xffffffffu, p, 1);
    p += __shfl_xor_sync(0xffffffffu, p, 2);

    float s   = fminf(fmaxf(p * 0.25f, -5.f), 5.f);
    float wgt = __expf(s);

    float w1 = __shfl_sync(0xffffffffu, wgt, lane | 4);
    float w2 = __shfl_sync(0xffffffffu, wgt, lane | 8);
    float w3 = __shfl_sync(0xffffffffu, wgt, lane | 12);
    if ((lane & 15) == 0) {
        float* sp = g_ssum + dst * 8 + (lane >> 2);
        asm volatile("red.global.add.v4.f32 [%0], {%1,%2,%3,%4};"
                     :: "l"(sp), "f"(wgt), "f"(w1), "f"(w2), "f"(w3) : "memory");
    }

    float4 v4 = reinterpret_cast<const float4*>(g_V)[src * 32 + lane];
    float* op = out + (size_t)dst * 128 + lane * 4;
    asm volatile("red.global.add.v4.f32 [%0], {%1,%2,%3,%4};"
                 :: "l"(op), "f"(v4.x * wgt), "f"(v4.y * wgt),
                    "f"(v4.z * wgt), "f"(v4.w * wgt) : "memory");
}

// ---------------- normalize: out /= (ssum + 1e-16) ------------------------
__global__ void norm_kernel(float4* __restrict__ out, int N) {
    int i = blockIdx.x * blockDim.x + threadIdx.x;
    if (i >= N * 32) return;
    float ss  = g_ssum[i >> 2];
    float inv = 1.f / (ss + 1e-16f);
    float4 v = out[i];
    v.x *= inv; v.y *= inv; v.z *= inv; v.w *= inv;
    out[i] = v;
}

// ---------------- launch ---------------------------------------------------
extern "C" void kernel_launch(void* const* d_in, const int* in_sizes, int n_in,
                              void* d_out, int out_size)
{
    const float* x   = (const float*)d_in[0];
    const float* ang = (const float*)d_in[1];
    const int*   ei  = (const int*)  d_in[2];
    const float* Wq  = (const float*)d_in[3];
    const float* bq  = (const float*)d_in[4];
    const float* Wk  = (const float*)d_in[5];
    const float* bk  = (const float*)d_in[6];
    const float* Wv  = (const float*)d_in[7];
    const float* bv  = (const float*)d_in[8];
    const float* S   = (const float*)d_in[9];
    float* out = (float*)d_out;

    int N = in_sizes[0] / 128;
    int E = in_sizes[2] / 2;

    cudaFuncSetAttribute(qkv_mma_kernel,
                         cudaFuncAttributeMaxDynamicSharedMemorySize, QKV_SMEM);

    zero_kernel<<<(N * 32 + 255) / 256, 256>>>((float4*)out, N);
    softmaxS_kernel<<<1, 256>>>(S);
    wconv_kernel<<<(3 * 16384 + 255) / 256, 256>>>(Wq, Wk, Wv);
    qkv_mma_kernel<<<(N + 63) / 64, 256, QKV_SMEM>>>(x, ang, bq, bk, bv, N);
    edge_kernel<<<(E + 7) / 8, 256>>>(ei, E, out);
    norm_kernel<<<(N * 32 + 255) / 256, 256>>>((float4*)out, N);
}

// round 6
// speedup vs baseline: 1.6527x; 1.0301x over previous
#include <cuda_runtime.h>
#include <cuda_bf16.h>
#include <cstdint>

#define N_NODES 50000
#define MAX_E   800000

// ---------------- device scratch ------------------------------------------
__device__ float g_Q[N_NODES * 128];
__device__ float g_K[N_NODES * 128];
__device__ float g_V[N_NODES * 128];
__device__ float g_P[256];                         // softmax(S): [4][64]
// W packed in mma b-frag order: [ph][kt:8][nt:16][lane:32][8 bf16: hi w0b0,w0b1,w1b0,w1b1, lo ...]
__device__ __nv_bfloat16 g_Wf[3 * 8 * 16 * 32 * 8];
// CSR scratch
__device__ int g_cnt[N_NODES + 1];
__device__ int g_off[N_NODES + 1];
__device__ int g_pos[N_NODES + 1];
__device__ int g_esrc[MAX_E];

// ---------------- helpers --------------------------------------------------
__device__ __forceinline__ uint32_t smem_u32(const void* p) {
    uint32_t a;
    asm("{ .reg .u64 t; cvta.to.shared.u64 t, %1; cvt.u32.u64 %0, t; }" : "=r"(a) : "l"(p));
    return a;
}
__device__ __forceinline__ void ldm_x4(uint32_t* r, uint32_t addr) {
    asm volatile("ldmatrix.sync.aligned.m8n8.x4.shared.b16 {%0,%1,%2,%3}, [%4];"
                 : "=r"(r[0]), "=r"(r[1]), "=r"(r[2]), "=r"(r[3]) : "r"(addr));
}
__device__ __forceinline__ void mma16816(float* d, const uint32_t* a, uint32_t b0, uint32_t b1) {
    asm volatile("mma.sync.aligned.m16n8k16.row.col.f32.bf16.bf16.f32 "
                 "{%0,%1,%2,%3}, {%4,%5,%6,%7}, {%8,%9}, {%0,%1,%2,%3};"
                 : "+f"(d[0]), "+f"(d[1]), "+f"(d[2]), "+f"(d[3])
                 : "r"(a[0]), "r"(a[1]), "r"(a[2]), "r"(a[3]), "r"(b0), "r"(b1));
}
__device__ __forceinline__ uint32_t pack_bf2(__nv_bfloat16 a, __nv_bfloat16 b) {
    return (uint32_t)__bfloat16_as_ushort(a) | ((uint32_t)__bfloat16_as_ushort(b) << 16);
}

// smem layout (bytes). x tiles: 64 rows x 136 bf16 (pitch 272B)
#define XH_OFF  0
#define XL_OFF  17408
#define OUT_OFF 34816                 // 64 x 132 f32
#define QKV_SMEM (34816 + 64 * 132 * 4)   // 68608

// ---------------- P = softmax(S, axis=1), S: [4][64] ----------------------
__global__ void softmaxS_kernel(const float* __restrict__ S) {
    int t = threadIdx.x;
    int a = t >> 6, c = t & 63;
    float v = __expf(S[a * 64 + c]);
    float s = v;
    #pragma unroll
    for (int o = 16; o; o >>= 1) s += __shfl_xor_sync(0xffffffffu, s, o);
    __shared__ float part[8];
    if ((t & 31) == 0) part[t >> 5] = s;
    __syncthreads();
    float sum = part[a * 2] + part[a * 2 + 1];
    g_P[a * 64 + c] = v / sum;
}

// ---------------- W[k][n] -> packed mma b-frags (bf16 hi/lo) --------------
__global__ void wconv_kernel(const float* __restrict__ Wq,
                             const float* __restrict__ Wk,
                             const float* __restrict__ Wv) {
    int i = blockIdx.x * blockDim.x + threadIdx.x;
    if (i >= 3 * 16384) return;
    int ph = i >> 14, rem = i & 16383;
    int k = rem >> 7, n = rem & 127;                 // coalesced read in n
    const float* W = (ph == 0) ? Wq : (ph == 1) ? Wk : Wv;
    float v = W[k * 128 + n];
    __nv_bfloat16 hi = __float2bfloat16_rn(v);
    __nv_bfloat16 lo = __float2bfloat16_rn(v - __bfloat162float(hi));
    int kt = k >> 4, nt = n >> 3;
    int t  = ((n & 7) << 2) | ((k & 7) >> 1);
    int word = (k >> 3) & 1, half = k & 1;
    size_t base = ((size_t)((ph * 8 + kt) * 16 + nt) * 32 + t) * 8;
    g_Wf[base + word * 2 + half]     = hi;
    g_Wf[base + 4 + word * 2 + half] = lo;
}

// ---------------- fused QKV GEMM (mma.sync bf16 split) + bias + RoPE ------
__global__ __launch_bounds__(256, 2) void qkv_mma_kernel(
    const float* __restrict__ x, const float* __restrict__ ang,
    const float* __restrict__ bq, const float* __restrict__ bk,
    const float* __restrict__ bv, int N)
{
    extern __shared__ char smem[];
    uint32_t sb = smem_u32(smem);
    int tid = threadIdx.x, wid = tid >> 5, lane = tid & 31;
    int row0 = blockIdx.x * 64;

    #pragma unroll
    for (int j = 0; j < 8; ++j) {
        int idx  = tid + 256 * j;
        int row  = idx >> 5;
        int col0 = (idx & 31) * 4;
        int gr   = row0 + row;
        float4 v = make_float4(0.f, 0.f, 0.f, 0.f);
        if (gr < N) v = *reinterpret_cast<const float4*>(&x[(size_t)gr * 128 + col0]);
        __nv_bfloat16 h0 = __float2bfloat16_rn(v.x), h1 = __float2bfloat16_rn(v.y);
        __nv_bfloat16 h2 = __float2bfloat16_rn(v.z), h3 = __float2bfloat16_rn(v.w);
        __nv_bfloat16 l0 = __float2bfloat16_rn(v.x - __bfloat162float(h0));
        __nv_bfloat16 l1 = __float2bfloat16_rn(v.y - __bfloat162float(h1));
        __nv_bfloat16 l2 = __float2bfloat16_rn(v.z - __bfloat162float(h2));
        __nv_bfloat16 l3 = __float2bfloat16_rn(v.w - __bfloat162float(h3));
        uint32_t off = (uint32_t)row * 272u + (uint32_t)col0 * 2u;
        *reinterpret_cast<uint2*>(smem + XH_OFF + off) = make_uint2(pack_bf2(h0, h1), pack_bf2(h2, h3));
        *reinterpret_cast<uint2*>(smem + XL_OFF + off) = make_uint2(pack_bf2(l0, l1), pack_bf2(l2, l3));
    }
    __syncthreads();

    int wm = wid & 3;
    int wn = wid >> 2;
    float* outs = reinterpret_cast<float*>(smem + OUT_OFF);

    for (int ph = 0; ph < 3; ++ph) {
        float d[8][4];
        #pragma unroll
        for (int nj = 0; nj < 8; ++nj)
            #pragma unroll
            for (int q = 0; q < 4; ++q) d[nj][q] = 0.f;

        const uint4* wf = reinterpret_cast<const uint4*>(g_Wf) + ((size_t)ph * 8 * 16 + wn * 8) * 32 + lane;

        #pragma unroll 2
        for (int kk = 0; kk < 8; ++kk) {
            uint32_t ah[4], al[4];
            {
                int r = wm * 16 + (lane & 15);
                int c = kk * 16 + (lane >> 4) * 8;
                uint32_t a = sb + XH_OFF + (uint32_t)r * 272u + (uint32_t)c * 2u;
                ldm_x4(ah, a);
                ldm_x4(al, a + (XL_OFF - XH_OFF));
            }
            uint4 bfr[8];
            #pragma unroll
            for (int nj = 0; nj < 8; ++nj)
                bfr[nj] = wf[((size_t)kk * 16 + nj) * 32];
            #pragma unroll
            for (int nj = 0; nj < 8; ++nj) {
                mma16816(d[nj], ah, bfr[nj].x, bfr[nj].y);
                mma16816(d[nj], ah, bfr[nj].z, bfr[nj].w);
                mma16816(d[nj], al, bfr[nj].x, bfr[nj].y);
            }
        }

        #pragma unroll
        for (int nj = 0; nj < 8; ++nj) {
            int r = wm * 16 + (lane >> 2);
            int c = wn * 64 + nj * 8 + 2 * (lane & 3);
            *reinterpret_cast<float2*>(&outs[r * 132 + c])       = make_float2(d[nj][0], d[nj][1]);
            *reinterpret_cast<float2*>(&outs[(r + 8) * 132 + c]) = make_float2(d[nj][2], d[nj][3]);
        }
        __syncthreads();

        {
            const float* bias = (ph == 0) ? bq : (ph == 1) ? bk : bv;
            float* gout = (ph == 0) ? g_Q : (ph == 1) ? g_K : g_V;
            #pragma unroll
            for (int rr = 0; rr < 8; ++rr) {
                int row = wid * 8 + rr;
                int n = row0 + row;
                if (n >= N) break;
                int j0 = lane * 4;
                const float* orow = &outs[row * 132];
                float v0 = orow[j0 + 0] + bias[j0 + 0];
                float v1 = orow[j0 + 1] + bias[j0 + 1];
                float v2 = orow[j0 + 2] + bias[j0 + 2];
                float v3 = orow[j0 + 3] + bias[j0 + 3];
                float4 ov;
                if (ph < 2) {
                    float a0 = ang[n * 4 + 0], a1 = ang[n * 4 + 1];
                    float a2 = ang[n * 4 + 2], a3 = ang[n * 4 + 3];
                    int m0 = 2 * lane, m1 = 2 * lane + 1;
                    float t0 = a0 * g_P[m0] + a1 * g_P[64 + m0] + a2 * g_P[128 + m0] + a3 * g_P[192 + m0];
                    float t1 = a0 * g_P[m1] + a1 * g_P[64 + m1] + a2 * g_P[128 + m1] + a3 * g_P[192 + m1];
                    float c0, s0, c1, s1;
                    __sincosf(t0, &s0, &c0);
                    __sincosf(t1, &s1, &c1);
                    float pv[4];
                    #pragma unroll
                    for (int i = 0; i < 4; ++i) {
                        int j = j0 + i;
                        int jj = j & 15, hb = j & 0x70;
                        int p; float sg;
                        if (jj < 8) { p = hb + 2 * jj + 1;  sg = -1.f; }
                        else        { p = hb + 2 * jj - 16; sg =  1.f; }
                        pv[i] = sg * (orow[p] + bias[p]);
                    }
                    ov.x = v0 * c0 + pv[0] * s0;
                    ov.y = v1 * c0 + pv[1] * s0;
                    ov.z = v2 * c1 + pv[2] * s1;
                    ov.w = v3 * c1 + pv[3] * s1;
                } else {
                    ov = make_float4(v0, v1, v2, v3);
                }
                *reinterpret_cast<float4*>(&gout[(size_t)n * 128 + j0]) = ov;
            }
        }
        __syncthreads();
    }
}

// ---------------- CSR build: zero counts, histogram, scan, scatter --------
__global__ void zero_cnt_kernel(int N) {
    int i = blockIdx.x * blockDim.x + threadIdx.x;
    if (i <= N) g_cnt[i] = 0;
}
__global__ void hist_kernel(const int* __restrict__ ei, int E) {
    int e = blockIdx.x * blockDim.x + threadIdx.x;
    if (e < E) atomicAdd(&g_cnt[ei[E + e]], 1);
}
__global__ __launch_bounds__(1024) void scan_kernel(int N) {
    __shared__ int sums[1024];
    int t = threadIdx.x;
    int chunk = (N + 1023) / 1024;
    int lo = t * chunk, hi = min(lo + chunk, N);
    int s = 0;
    for (int i = lo; i < hi; ++i) s += g_cnt[i];
    sums[t] = s;
    __syncthreads();
    #pragma unroll
    for (int off = 1; off < 1024; off <<= 1) {
        int v = (t >= off) ? sums[t - off] : 0;
        __syncthreads();
        sums[t] += v;
        __syncthreads();
    }
    int base = sums[t] - s;                 // exclusive prefix for this chunk
    for (int i = lo; i < hi; ++i) {
        g_off[i] = base;
        g_pos[i] = base;
        base += g_cnt[i];
    }
    if (t == 1023) g_off[N] = sums[1023];
}
__global__ void scatter_kernel(const int* __restrict__ ei, int E) {
    int e = blockIdx.x * blockDim.x + threadIdx.x;
    if (e >= E) return;
    int src = ei[e];
    int dst = ei[E + e];
    int p = atomicAdd(&g_pos[dst], 1);
    g_esrc[p] = src;
}

// ---------------- aggregation: warp per dst node --------------------------
__global__ __launch_bounds__(256) void agg_kernel(float* __restrict__ out, int N) {
    int w    = (blockIdx.x * blockDim.x + threadIdx.x) >> 5;
    int lane = threadIdx.x & 31;
    if (w >= N) return;
    int d = w;
    int beg = g_off[d], end = g_off[d + 1];

    float4 q4 = reinterpret_cast<const float4*>(g_Q)[d * 32 + lane];
    float4 acc = make_float4(0.f, 0.f, 0.f, 0.f);
    float ssum = 0.f;

    int src = (beg < end) ? g_esrc[beg] : 0;
    for (int i = beg; i < end; ++i) {
        int nsrc = (i + 1 < end) ? g_esrc[i + 1] : 0;
        float4 k4 = reinterpret_cast<const float4*>(g_K)[src * 32 + lane];
        float4 v4 = reinterpret_cast<const float4*>(g_V)[src * 32 + lane];
        float p = k4.x * q4.x + k4.y * q4.y + k4.z * q4.z + k4.w * q4.w;
        p += __shfl_xor_sync(0xffffffffu, p, 1);
        p += __shfl_xor_sync(0xffffffffu, p, 2);   // 4-lane head reduction
        float s   = fminf(fmaxf(p * 0.25f, -5.f), 5.f);
        float wgt = __expf(s);
        ssum += wgt;
        acc.x += wgt * v4.x; acc.y += wgt * v4.y;
        acc.z += wgt * v4.z; acc.w += wgt * v4.w;
        src = nsrc;
    }
    float inv = 1.f / (ssum + 1e-16f);
    reinterpret_cast<float4*>(out)[d * 32 + lane] =
        make_float4(acc.x * inv, acc.y * inv, acc.z * inv, acc.w * inv);
}

// ---------------- launch ---------------------------------------------------
extern "C" void kernel_launch(void* const* d_in, const int* in_sizes, int n_in,
                              void* d_out, int out_size)
{
    const float* x   = (const float*)d_in[0];
    const float* ang = (const float*)d_in[1];
    const int*   ei  = (const int*)  d_in[2];
    const float* Wq  = (const float*)d_in[3];
    const float* bq  = (const float*)d_in[4];
    const float* Wk  = (const float*)d_in[5];
    const float* bk  = (const float*)d_in[6];
    const float* Wv  = (const float*)d_in[7];
    const float* bv  = (const float*)d_in[8];
    const float* S   = (const float*)d_in[9];
    float* out = (float*)d_out;

    int N = in_sizes[0] / 128;
    int E = in_sizes[2] / 2;

    cudaFuncSetAttribute(qkv_mma_kernel,
                         cudaFuncAttributeMaxDynamicSharedMemorySize, QKV_SMEM);

    softmaxS_kernel<<<1, 256>>>(S);
    wconv_kernel<<<(3 * 16384 + 255) / 256, 256>>>(Wq, Wk, Wv);

    zero_cnt_kernel<<<(N + 256) / 256, 256>>>(N);
    hist_kernel<<<(E + 255) / 256, 256>>>(ei, E);
    scan_kernel<<<1, 1024>>>(N);
    scatter_kernel<<<(E + 255) / 256, 256>>>(ei, E);

    qkv_mma_kernel<<<(N + 63) / 64, 256, QKV_SMEM>>>(x, ang, bq, bk, bv, N);

    agg_kernel<<<(N + 7) / 8, 256>>>(out, N);
}

// round 7
// speedup vs baseline: 1.6664x; 1.0083x over previous
#include <cuda_runtime.h>
#include <cuda_bf16.h>
#include <cstdint>

#define N_NODES 50000
#define MAX_E   800000

// ---------------- device scratch ------------------------------------------
__device__ float g_Q[N_NODES * 128];
__device__ float g_KV[N_NODES * 256];              // [node][K:128 | V:128]
__device__ float g_P[256];                         // softmax(S): [4][64]
// W packed in mma b-frag order: [ph][kt:8][nt:16][lane:32][8 bf16: hi w0b0,w0b1,w1b0,w1b1, lo ...]
__device__ __nv_bfloat16 g_Wf[3 * 8 * 16 * 32 * 8];
// CSR scratch
__device__ int g_cnt[N_NODES + 1];
__device__ int g_off[N_NODES + 1];
__device__ int g_pos[N_NODES + 1];
__device__ int g_esrc[MAX_E];

// ---------------- helpers --------------------------------------------------
__device__ __forceinline__ uint32_t smem_u32(const void* p) {
    uint32_t a;
    asm("{ .reg .u64 t; cvta.to.shared.u64 t, %1; cvt.u32.u64 %0, t; }" : "=r"(a) : "l"(p));
    return a;
}
__device__ __forceinline__ void ldm_x4(uint32_t* r, uint32_t addr) {
    asm volatile("ldmatrix.sync.aligned.m8n8.x4.shared.b16 {%0,%1,%2,%3}, [%4];"
                 : "=r"(r[0]), "=r"(r[1]), "=r"(r[2]), "=r"(r[3]) : "r"(addr));
}
__device__ __forceinline__ void mma16816(float* d, const uint32_t* a, uint32_t b0, uint32_t b1) {
    asm volatile("mma.sync.aligned.m16n8k16.row.col.f32.bf16.bf16.f32 "
                 "{%0,%1,%2,%3}, {%4,%5,%6,%7}, {%8,%9}, {%0,%1,%2,%3};"
                 : "+f"(d[0]), "+f"(d[1]), "+f"(d[2]), "+f"(d[3])
                 : "r"(a[0]), "r"(a[1]), "r"(a[2]), "r"(a[3]), "r"(b0), "r"(b1));
}
__device__ __forceinline__ uint32_t pack_bf2(__nv_bfloat16 a, __nv_bfloat16 b) {
    return (uint32_t)__bfloat16_as_ushort(a) | ((uint32_t)__bfloat16_as_ushort(b) << 16);
}

// smem layout (bytes). x tiles: 64 rows x 136 bf16 (pitch 272B)
#define XH_OFF  0
#define XL_OFF  17408
#define OUT_OFF 34816                 // 64 x 132 f32
#define QKV_SMEM (34816 + 64 * 132 * 4)   // 68608

// ---------------- P = softmax(S, axis=1), S: [4][64] ----------------------
__global__ void softmaxS_kernel(const float* __restrict__ S) {
    int t = threadIdx.x;
    int a = t >> 6, c = t & 63;
    float v = __expf(S[a * 64 + c]);
    float s = v;
    #pragma unroll
    for (int o = 16; o; o >>= 1) s += __shfl_xor_sync(0xffffffffu, s, o);
    __shared__ float part[8];
    if ((t & 31) == 0) part[t >> 5] = s;
    __syncthreads();
    float sum = part[a * 2] + part[a * 2 + 1];
    g_P[a * 64 + c] = v / sum;
}

// ---------------- W[k][n] -> packed mma b-frags (bf16 hi/lo) --------------
__global__ void wconv_kernel(const float* __restrict__ Wq,
                             const float* __restrict__ Wk,
                             const float* __restrict__ Wv) {
    int i = blockIdx.x * blockDim.x + threadIdx.x;
    if (i >= 3 * 16384) return;
    int ph = i >> 14, rem = i & 16383;
    int k = rem >> 7, n = rem & 127;                 // coalesced read in n
    const float* W = (ph == 0) ? Wq : (ph == 1) ? Wk : Wv;
    float v = W[k * 128 + n];
    __nv_bfloat16 hi = __float2bfloat16_rn(v);
    __nv_bfloat16 lo = __float2bfloat16_rn(v - __bfloat162float(hi));
    int kt = k >> 4, nt = n >> 3;
    int t  = ((n & 7) << 2) | ((k & 7) >> 1);
    int word = (k >> 3) & 1, half = k & 1;
    size_t base = ((size_t)((ph * 8 + kt) * 16 + nt) * 32 + t) * 8;
    g_Wf[base + word * 2 + half]     = hi;
    g_Wf[base + 4 + word * 2 + half] = lo;
}

// ---------------- fused QKV GEMM (mma.sync bf16 split) + bias + RoPE ------
__global__ __launch_bounds__(256, 2) void qkv_mma_kernel(
    const float* __restrict__ x, const float* __restrict__ ang,
    const float* __restrict__ bq, const float* __restrict__ bk,
    const float* __restrict__ bv, int N)
{
    extern __shared__ char smem[];
    uint32_t sb = smem_u32(smem);
    int tid = threadIdx.x, wid = tid >> 5, lane = tid & 31;
    int row0 = blockIdx.x * 64;

    #pragma unroll
    for (int j = 0; j < 8; ++j) {
        int idx  = tid + 256 * j;
        int row  = idx >> 5;
        int col0 = (idx & 31) * 4;
        int gr   = row0 + row;
        float4 v = make_float4(0.f, 0.f, 0.f, 0.f);
        if (gr < N) v = *reinterpret_cast<const float4*>(&x[(size_t)gr * 128 + col0]);
        __nv_bfloat16 h0 = __float2bfloat16_rn(v.x), h1 = __float2bfloat16_rn(v.y);
        __nv_bfloat16 h2 = __float2bfloat16_rn(v.z), h3 = __float2bfloat16_rn(v.w);
        __nv_bfloat16 l0 = __float2bfloat16_rn(v.x - __bfloat162float(h0));
        __nv_bfloat16 l1 = __float2bfloat16_rn(v.y - __bfloat162float(h1));
        __nv_bfloat16 l2 = __float2bfloat16_rn(v.z - __bfloat162float(h2));
        __nv_bfloat16 l3 = __float2bfloat16_rn(v.w - __bfloat162float(h3));
        uint32_t off = (uint32_t)row * 272u + (uint32_t)col0 * 2u;
        *reinterpret_cast<uint2*>(smem + XH_OFF + off) = make_uint2(pack_bf2(h0, h1), pack_bf2(h2, h3));
        *reinterpret_cast<uint2*>(smem + XL_OFF + off) = make_uint2(pack_bf2(l0, l1), pack_bf2(l2, l3));
    }
    __syncthreads();

    int wm = wid & 3;
    int wn = wid >> 2;
    float* outs = reinterpret_cast<float*>(smem + OUT_OFF);

    for (int ph = 0; ph < 3; ++ph) {
        float d[8][4];
        #pragma unroll
        for (int nj = 0; nj < 8; ++nj)
            #pragma unroll
            for (int q = 0; q < 4; ++q) d[nj][q] = 0.f;

        const uint4* wf = reinterpret_cast<const uint4*>(g_Wf) + ((size_t)ph * 8 * 16 + wn * 8) * 32 + lane;

        #pragma unroll 2
        for (int kk = 0; kk < 8; ++kk) {
            uint32_t ah[4], al[4];
            {
                int r = wm * 16 + (lane & 15);
                int c = kk * 16 + (lane >> 4) * 8;
                uint32_t a = sb + XH_OFF + (uint32_t)r * 272u + (uint32_t)c * 2u;
                ldm_x4(ah, a);
                ldm_x4(al, a + (XL_OFF - XH_OFF));
            }
            uint4 bfr[8];
            #pragma unroll
            for (int nj = 0; nj < 8; ++nj)
                bfr[nj] = wf[((size_t)kk * 16 + nj) * 32];
            #pragma unroll
            for (int nj = 0; nj < 8; ++nj) {
                mma16816(d[nj], ah, bfr[nj].x, bfr[nj].y);
                mma16816(d[nj], ah, bfr[nj].z, bfr[nj].w);
                mma16816(d[nj], al, bfr[nj].x, bfr[nj].y);
            }
        }

        #pragma unroll
        for (int nj = 0; nj < 8; ++nj) {
            int r = wm * 16 + (lane >> 2);
            int c = wn * 64 + nj * 8 + 2 * (lane & 3);
            *reinterpret_cast<float2*>(&outs[r * 132 + c])       = make_float2(d[nj][0], d[nj][1]);
            *reinterpret_cast<float2*>(&outs[(r + 8) * 132 + c]) = make_float2(d[nj][2], d[nj][3]);
        }
        __syncthreads();

        {
            const float* bias = (ph == 0) ? bq : (ph == 1) ? bk : bv;
            #pragma unroll
            for (int rr = 0; rr < 8; ++rr) {
                int row = wid * 8 + rr;
                int n = row0 + row;
                if (n >= N) break;
                int j0 = lane * 4;
                const float* orow = &outs[row * 132];
                float v0 = orow[j0 + 0] + bias[j0 + 0];
                float v1 = orow[j0 + 1] + bias[j0 + 1];
                float v2 = orow[j0 + 2] + bias[j0 + 2];
                float v3 = orow[j0 + 3] + bias[j0 + 3];
                float4 ov;
                if (ph < 2) {
                    float a0 = ang[n * 4 + 0], a1 = ang[n * 4 + 1];
                    float a2 = ang[n * 4 + 2], a3 = ang[n * 4 + 3];
                    int m0 = 2 * lane, m1 = 2 * lane + 1;
                    float t0 = a0 * g_P[m0] + a1 * g_P[64 + m0] + a2 * g_P[128 + m0] + a3 * g_P[192 + m0];
                    float t1 = a0 * g_P[m1] + a1 * g_P[64 + m1] + a2 * g_P[128 + m1] + a3 * g_P[192 + m1];
                    float c0, s0, c1, s1;
                    __sincosf(t0, &s0, &c0);
                    __sincosf(t1, &s1, &c1);
                    float pv[4];
                    #pragma unroll
                    for (int i = 0; i < 4; ++i) {
                        int j = j0 + i;
                        int jj = j & 15, hb = j & 0x70;
                        int p; float sg;
                        if (jj < 8) { p = hb + 2 * jj + 1;  sg = -1.f; }
                        else        { p = hb + 2 * jj - 16; sg =  1.f; }
                        pv[i] = sg * (orow[p] + bias[p]);
                    }
                    ov.x = v0 * c0 + pv[0] * s0;
                    ov.y = v1 * c0 + pv[1] * s0;
                    ov.z = v2 * c1 + pv[2] * s1;
                    ov.w = v3 * c1 + pv[3] * s1;
                } else {
                    ov = make_float4(v0, v1, v2, v3);
                }
                float* gout;
                size_t gi;
                if (ph == 0)      { gout = g_Q;  gi = (size_t)n * 128 + j0; }
                else if (ph == 1) { gout = g_KV; gi = (size_t)n * 256 + j0; }
                else              { gout = g_KV; gi = (size_t)n * 256 + 128 + j0; }
                *reinterpret_cast<float4*>(&gout[gi]) = ov;
            }
        }
        __syncthreads();
    }
}

// ---------------- CSR build: zero counts, histogram, scan, scatter --------
__global__ void zero_cnt_kernel(int N) {
    int i = blockIdx.x * blockDim.x + threadIdx.x;
    if (i <= N) g_cnt[i] = 0;
}
__global__ void hist_kernel(const int* __restrict__ ei, int E) {
    int e = blockIdx.x * blockDim.x + threadIdx.x;
    if (e < E) atomicAdd(&g_cnt[ei[E + e]], 1);
}
__global__ __launch_bounds__(1024) void scan_kernel(int N) {
    __shared__ int sums[1024];
    int t = threadIdx.x;
    int chunk = (N + 1023) / 1024;
    int lo = t * chunk, hi = min(lo + chunk, N);
    int s = 0;
    for (int i = lo; i < hi; ++i) s += g_cnt[i];
    sums[t] = s;
    __syncthreads();
    #pragma unroll
    for (int off = 1; off < 1024; off <<= 1) {
        int v = (t >= off) ? sums[t - off] : 0;
        __syncthreads();
        sums[t] += v;
        __syncthreads();
    }
    int base = sums[t] - s;
    for (int i = lo; i < hi; ++i) {
        g_off[i] = base;
        g_pos[i] = base;
        base += g_cnt[i];
    }
    if (t == 1023) g_off[N] = sums[1023];
}
__global__ void scatter_kernel(const int* __restrict__ ei, int E) {
    int e = blockIdx.x * blockDim.x + threadIdx.x;
    if (e >= E) return;
    int src = ei[e];
    int dst = ei[E + e];
    int p = atomicAdd(&g_pos[dst], 1);
    g_esrc[p] = src;
}

// ---------------- aggregation: warp per dst node, 4-edge batches ----------
__global__ __launch_bounds__(256) void agg_kernel(float* __restrict__ out, int N) {
    int w    = (blockIdx.x * blockDim.x + threadIdx.x) >> 5;
    int lane = threadIdx.x & 31;
    if (w >= N) return;
    int beg = g_off[w], end = g_off[w + 1];

    float4 q4 = reinterpret_cast<const float4*>(g_Q)[w * 32 + lane];
    float4 acc = make_float4(0.f, 0.f, 0.f, 0.f);
    float ssum = 0.f;
    const float4* kv = reinterpret_cast<const float4*>(g_KV);

    for (int i = beg; i < end; i += 4) {
        int s0 = g_esrc[i];
        int s1 = (i + 1 < end) ? g_esrc[i + 1] : -1;
        int s2 = (i + 2 < end) ? g_esrc[i + 2] : -1;
        int s3 = (i + 3 < end) ? g_esrc[i + 3] : -1;
        int a0 = s0, a1 = (s1 < 0) ? 0 : s1, a2 = (s2 < 0) ? 0 : s2, a3 = (s3 < 0) ? 0 : s3;
        // issue all 8 loads before any compute
        float4 k0 = kv[a0 * 64 + lane];
        float4 k1 = kv[a1 * 64 + lane];
        float4 k2 = kv[a2 * 64 + lane];
        float4 k3 = kv[a3 * 64 + lane];
        float4 v0 = kv[a0 * 64 + 32 + lane];
        float4 v1 = kv[a1 * 64 + 32 + lane];
        float4 v2 = kv[a2 * 64 + 32 + lane];
        float4 v3 = kv[a3 * 64 + 32 + lane];

        float p0 = k0.x * q4.x + k0.y * q4.y + k0.z * q4.z + k0.w * q4.w;
        float p1 = k1.x * q4.x + k1.y * q4.y + k1.z * q4.z + k1.w * q4.w;
        float p2 = k2.x * q4.x + k2.y * q4.y + k2.z * q4.z + k2.w * q4.w;
        float p3 = k3.x * q4.x + k3.y * q4.y + k3.z * q4.z + k3.w * q4.w;
        p0 += __shfl_xor_sync(0xffffffffu, p0, 1);
        p1 += __shfl_xor_sync(0xffffffffu, p1, 1);
        p2 += __shfl_xor_sync(0xffffffffu, p2, 1);
        p3 += __shfl_xor_sync(0xffffffffu, p3, 1);
        p0 += __shfl_xor_sync(0xffffffffu, p0, 2);
        p1 += __shfl_xor_sync(0xffffffffu, p1, 2);
        p2 += __shfl_xor_sync(0xffffffffu, p2, 2);
        p3 += __shfl_xor_sync(0xffffffffu, p3, 2);

        float w0 = __expf(fminf(fmaxf(p0 * 0.25f, -5.f), 5.f));
        float w1 = (s1 < 0) ? 0.f : __expf(fminf(fmaxf(p1 * 0.25f, -5.f), 5.f));
        float w2 = (s2 < 0) ? 0.f : __expf(fminf(fmaxf(p2 * 0.25f, -5.f), 5.f));
        float w3 = (s3 < 0) ? 0.f : __expf(fminf(fmaxf(p3 * 0.25f, -5.f), 5.f));

        ssum += (w0 + w1) + (w2 + w3);
        acc.x += w0 * v0.x + w1 * v1.x + w2 * v2.x + w3 * v3.x;
        acc.y += w0 * v0.y + w1 * v1.y + w2 * v2.y + w3 * v3.y;
        acc.z += w0 * v0.z + w1 * v1.z + w2 * v2.z + w3 * v3.z;
        acc.w += w0 * v0.w + w1 * v1.w + w2 * v2.w + w3 * v3.w;
    }
    float inv = 1.f / (ssum + 1e-16f);
    reinterpret_cast<float4*>(out)[w * 32 + lane] =
        make_float4(acc.x * inv, acc.y * inv, acc.z * inv, acc.w * inv);
}

// ---------------- launch ---------------------------------------------------
extern "C" void kernel_launch(void* const* d_in, const int* in_sizes, int n_in,
                              void* d_out, int out_size)
{
    const float* x   = (const float*)d_in[0];
    const float* ang = (const float*)d_in[1];
    const int*   ei  = (const int*)  d_in[2];
    const float* Wq  = (const float*)d_in[3];
    const float* bq  = (const float*)d_in[4];
    const float* Wk  = (const float*)d_in[5];
    const float* bk  = (const float*)d_in[6];
    const float* Wv  = (const float*)d_in[7];
    const float* bv  = (const float*)d_in[8];
    const float* S   = (const float*)d_in[9];
    float* out = (float*)d_out;

    int N = in_sizes[0] / 128;
    int E = in_sizes[2] / 2;

    cudaFuncSetAttribute(qkv_mma_kernel,
                         cudaFuncAttributeMaxDynamicSharedMemorySize, QKV_SMEM);

    softmaxS_kernel<<<1, 256>>>(S);
    wconv_kernel<<<(3 * 16384 + 255) / 256, 256>>>(Wq, Wk, Wv);

    zero_cnt_kernel<<<(N + 256) / 256, 256>>>(N);
    hist_kernel<<<(E + 255) / 256, 256>>>(ei, E);
    scan_kernel<<<1, 1024>>>(N);
    scatter_kernel<<<(E + 255) / 256, 256>>>(ei, E);

    qkv_mma_kernel<<<(N + 63) / 64, 256, QKV_SMEM>>>(x, ang, bq, bk, bv, N);

    agg_kernel<<<(N + 7) / 8, 256>>>(out, N);
}

// round 8
// speedup vs baseline: 1.7147x; 1.0290x over previous
#include <cuda_runtime.h>
#include <cuda_bf16.h>
#include <cuda_fp16.h>
#include <cstdint>

#define N_NODES 50000
#define MAX_E   800000

// ---------------- device scratch ------------------------------------------
__device__ float g_Q[N_NODES * 128];
__device__ __half g_KVh[N_NODES * 256];            // [node][K:128 | V:128] fp16
__device__ float g_P[256];                         // softmax(S): [4][64]
// W packed in mma b-frag order: [ph][kt:8][nt:16][lane:32][8 bf16: hi w0b0,w0b1,w1b0,w1b1, lo ...]
__device__ __nv_bfloat16 g_Wf[3 * 8 * 16 * 32 * 8];
// CSR scratch
__device__ int g_cnt[N_NODES + 1];
__device__ int g_off[N_NODES + 1];
__device__ int g_pos[N_NODES + 1];
__device__ int g_esrc[MAX_E];

// ---------------- helpers --------------------------------------------------
__device__ __forceinline__ uint32_t smem_u32(const void* p) {
    uint32_t a;
    asm("{ .reg .u64 t; cvta.to.shared.u64 t, %1; cvt.u32.u64 %0, t; }" : "=r"(a) : "l"(p));
    return a;
}
__device__ __forceinline__ void ldm_x4(uint32_t* r, uint32_t addr) {
    asm volatile("ldmatrix.sync.aligned.m8n8.x4.shared.b16 {%0,%1,%2,%3}, [%4];"
                 : "=r"(r[0]), "=r"(r[1]), "=r"(r[2]), "=r"(r[3]) : "r"(addr));
}
__device__ __forceinline__ void mma16816(float* d, const uint32_t* a, uint32_t b0, uint32_t b1) {
    asm volatile("mma.sync.aligned.m16n8k16.row.col.f32.bf16.bf16.f32 "
                 "{%0,%1,%2,%3}, {%4,%5,%6,%7}, {%8,%9}, {%0,%1,%2,%3};"
                 : "+f"(d[0]), "+f"(d[1]), "+f"(d[2]), "+f"(d[3])
                 : "r"(a[0]), "r"(a[1]), "r"(a[2]), "r"(a[3]), "r"(b0), "r"(b1));
}
__device__ __forceinline__ uint32_t pack_bf2(__nv_bfloat16 a, __nv_bfloat16 b) {
    return (uint32_t)__bfloat16_as_ushort(a) | ((uint32_t)__bfloat16_as_ushort(b) << 16);
}

// smem layout (bytes). x tiles: 64 rows x 136 bf16 (pitch 272B)
#define XH_OFF  0
#define XL_OFF  17408
#define OUT_OFF 34816                 // 64 x 132 f32
#define QKV_SMEM (34816 + 64 * 132 * 4)   // 68608

// ---------------- P = softmax(S, axis=1), S: [4][64] ----------------------
__global__ void softmaxS_kernel(const float* __restrict__ S) {
    int t = threadIdx.x;
    int a = t >> 6, c = t & 63;
    float v = __expf(S[a * 64 + c]);
    float s = v;
    #pragma unroll
    for (int o = 16; o; o >>= 1) s += __shfl_xor_sync(0xffffffffu, s, o);
    __shared__ float part[8];
    if ((t & 31) == 0) part[t >> 5] = s;
    __syncthreads();
    float sum = part[a * 2] + part[a * 2 + 1];
    g_P[a * 64 + c] = v / sum;
}

// ---------------- W[k][n] -> packed mma b-frags (bf16 hi/lo) --------------
__global__ void wconv_kernel(const float* __restrict__ Wq,
                             const float* __restrict__ Wk,
                             const float* __restrict__ Wv) {
    int i = blockIdx.x * blockDim.x + threadIdx.x;
    if (i >= 3 * 16384) return;
    int ph = i >> 14, rem = i & 16383;
    int k = rem >> 7, n = rem & 127;                 // coalesced read in n
    const float* W = (ph == 0) ? Wq : (ph == 1) ? Wk : Wv;
    float v = W[k * 128 + n];
    __nv_bfloat16 hi = __float2bfloat16_rn(v);
    __nv_bfloat16 lo = __float2bfloat16_rn(v - __bfloat162float(hi));
    int kt = k >> 4, nt = n >> 3;
    int t  = ((n & 7) << 2) | ((k & 7) >> 1);
    int word = (k >> 3) & 1, half = k & 1;
    size_t base = ((size_t)((ph * 8 + kt) * 16 + nt) * 32 + t) * 8;
    g_Wf[base + word * 2 + half]     = hi;
    g_Wf[base + 4 + word * 2 + half] = lo;
}

// ---------------- fused QKV GEMM (mma.sync bf16 split) + bias + RoPE ------
__global__ __launch_bounds__(256, 2) void qkv_mma_kernel(
    const float* __restrict__ x, const float* __restrict__ ang,
    const float* __restrict__ bq, const float* __restrict__ bk,
    const float* __restrict__ bv, int N)
{
    extern __shared__ char smem[];
    uint32_t sb = smem_u32(smem);
    int tid = threadIdx.x, wid = tid >> 5, lane = tid & 31;
    int row0 = blockIdx.x * 64;

    #pragma unroll
    for (int j = 0; j < 8; ++j) {
        int idx  = tid + 256 * j;
        int row  = idx >> 5;
        int col0 = (idx & 31) * 4;
        int gr   = row0 + row;
        float4 v = make_float4(0.f, 0.f, 0.f, 0.f);
        if (gr < N) v = *reinterpret_cast<const float4*>(&x[(size_t)gr * 128 + col0]);
        __nv_bfloat16 h0 = __float2bfloat16_rn(v.x), h1 = __float2bfloat16_rn(v.y);
        __nv_bfloat16 h2 = __float2bfloat16_rn(v.z), h3 = __float2bfloat16_rn(v.w);
        __nv_bfloat16 l0 = __float2bfloat16_rn(v.x - __bfloat162float(h0));
        __nv_bfloat16 l1 = __float2bfloat16_rn(v.y - __bfloat162float(h1));
        __nv_bfloat16 l2 = __float2bfloat16_rn(v.z - __bfloat162float(h2));
        __nv_bfloat16 l3 = __float2bfloat16_rn(v.w - __bfloat162float(h3));
        uint32_t off = (uint32_t)row * 272u + (uint32_t)col0 * 2u;
        *reinterpret_cast<uint2*>(smem + XH_OFF + off) = make_uint2(pack_bf2(h0, h1), pack_bf2(h2, h3));
        *reinterpret_cast<uint2*>(smem + XL_OFF + off) = make_uint2(pack_bf2(l0, l1), pack_bf2(l2, l3));
    }
    __syncthreads();

    int wm = wid & 3;
    int wn = wid >> 2;
    float* outs = reinterpret_cast<float*>(smem + OUT_OFF);

    for (int ph = 0; ph < 3; ++ph) {
        float d[8][4];
        #pragma unroll
        for (int nj = 0; nj < 8; ++nj)
            #pragma unroll
            for (int q = 0; q < 4; ++q) d[nj][q] = 0.f;

        const uint4* wf = reinterpret_cast<const uint4*>(g_Wf) + ((size_t)ph * 8 * 16 + wn * 8) * 32 + lane;

        #pragma unroll 2
        for (int kk = 0; kk < 8; ++kk) {
            uint32_t ah[4], al[4];
            {
                int r = wm * 16 + (lane & 15);
                int c = kk * 16 + (lane >> 4) * 8;
                uint32_t a = sb + XH_OFF + (uint32_t)r * 272u + (uint32_t)c * 2u;
                ldm_x4(ah, a);
                ldm_x4(al, a + (XL_OFF - XH_OFF));
            }
            uint4 bfr[8];
            #pragma unroll
            for (int nj = 0; nj < 8; ++nj)
                bfr[nj] = wf[((size_t)kk * 16 + nj) * 32];
            #pragma unroll
            for (int nj = 0; nj < 8; ++nj) {
                mma16816(d[nj], ah, bfr[nj].x, bfr[nj].y);
                mma16816(d[nj], ah, bfr[nj].z, bfr[nj].w);
                mma16816(d[nj], al, bfr[nj].x, bfr[nj].y);
            }
        }

        #pragma unroll
        for (int nj = 0; nj < 8; ++nj) {
            int r = wm * 16 + (lane >> 2);
            int c = wn * 64 + nj * 8 + 2 * (lane & 3);
            *reinterpret_cast<float2*>(&outs[r * 132 + c])       = make_float2(d[nj][0], d[nj][1]);
            *reinterpret_cast<float2*>(&outs[(r + 8) * 132 + c]) = make_float2(d[nj][2], d[nj][3]);
        }
        __syncthreads();

        {
            const float* bias = (ph == 0) ? bq : (ph == 1) ? bk : bv;
            #pragma unroll
            for (int rr = 0; rr < 8; ++rr) {
                int row = wid * 8 + rr;
                int n = row0 + row;
                if (n >= N) break;
                int j0 = lane * 4;
                const float* orow = &outs[row * 132];
                float v0 = orow[j0 + 0] + bias[j0 + 0];
                float v1 = orow[j0 + 1] + bias[j0 + 1];
                float v2 = orow[j0 + 2] + bias[j0 + 2];
                float v3 = orow[j0 + 3] + bias[j0 + 3];
                float4 ov;
                if (ph < 2) {
                    float a0 = ang[n * 4 + 0], a1 = ang[n * 4 + 1];
                    float a2 = ang[n * 4 + 2], a3 = ang[n * 4 + 3];
                    int m0 = 2 * lane, m1 = 2 * lane + 1;
                    float t0 = a0 * g_P[m0] + a1 * g_P[64 + m0] + a2 * g_P[128 + m0] + a3 * g_P[192 + m0];
                    float t1 = a0 * g_P[m1] + a1 * g_P[64 + m1] + a2 * g_P[128 + m1] + a3 * g_P[192 + m1];
                    float c0, s0, c1, s1;
                    __sincosf(t0, &s0, &c0);
                    __sincosf(t1, &s1, &c1);
                    float pv[4];
                    #pragma unroll
                    for (int i = 0; i < 4; ++i) {
                        int j = j0 + i;
                        int jj = j & 15, hb = j & 0x70;
                        int p; float sg;
                        if (jj < 8) { p = hb + 2 * jj + 1;  sg = -1.f; }
                        else        { p = hb + 2 * jj - 16; sg =  1.f; }
                        pv[i] = sg * (orow[p] + bias[p]);
                    }
                    ov.x = v0 * c0 + pv[0] * s0;
                    ov.y = v1 * c0 + pv[1] * s0;
                    ov.z = v2 * c1 + pv[2] * s1;
                    ov.w = v3 * c1 + pv[3] * s1;
                } else {
                    ov = make_float4(v0, v1, v2, v3);
                }
                if (ph == 0) {
                    *reinterpret_cast<float4*>(&g_Q[(size_t)n * 128 + j0]) = ov;
                } else {
                    // pack to fp16: K at halves [0,128), V at [128,256)
                    __half2 h01 = __floats2half2_rn(ov.x, ov.y);
                    __half2 h23 = __floats2half2_rn(ov.z, ov.w);
                    uint2 pk = make_uint2(*reinterpret_cast<uint32_t*>(&h01),
                                          *reinterpret_cast<uint32_t*>(&h23));
                    size_t gi = (size_t)n * 256 + (ph == 1 ? 0 : 128) + j0;
                    *reinterpret_cast<uint2*>(&g_KVh[gi]) = pk;
                }
            }
        }
        __syncthreads();
    }
}

// ---------------- CSR build: zero counts, histogram, scan, scatter --------
__global__ void zero_cnt_kernel(int N) {
    int i = blockIdx.x * blockDim.x + threadIdx.x;
    if (i <= N) g_cnt[i] = 0;
}
__global__ void hist_kernel(const int* __restrict__ ei, int E) {
    int e = blockIdx.x * blockDim.x + threadIdx.x;
    if (e < E) atomicAdd(&g_cnt[ei[E + e]], 1);
}
__global__ __launch_bounds__(1024) void scan_kernel(int N) {
    __shared__ int sums[1024];
    int t = threadIdx.x;
    int chunk = (N + 1023) / 1024;
    int lo = t * chunk, hi = min(lo + chunk, N);
    int s = 0;
    for (int i = lo; i < hi; ++i) s += g_cnt[i];
    sums[t] = s;
    __syncthreads();
    #pragma unroll
    for (int off = 1; off < 1024; off <<= 1) {
        int v = (t >= off) ? sums[t - off] : 0;
        __syncthreads();
        sums[t] += v;
        __syncthreads();
    }
    int base = sums[t] - s;
    for (int i = lo; i < hi; ++i) {
        g_off[i] = base;
        g_pos[i] = base;
        base += g_cnt[i];
    }
    if (t == 1023) g_off[N] = sums[1023];
}
__global__ void scatter_kernel(const int* __restrict__ ei, int E) {
    int e = blockIdx.x * blockDim.x + threadIdx.x;
    if (e >= E) return;
    int src = ei[e];
    int dst = ei[E + e];
    int p = atomicAdd(&g_pos[dst], 1);
    g_esrc[p] = src;
}

// ---------------- aggregation: warp per dst node, fp16 K/V ----------------
__global__ __launch_bounds__(256) void agg_kernel(float* __restrict__ out, int N) {
    int w    = (blockIdx.x * blockDim.x + threadIdx.x) >> 5;
    int lane = threadIdx.x & 31;
    if (w >= N) return;
    int beg = g_off[w], end = g_off[w + 1];

    float4 q4 = reinterpret_cast<const float4*>(g_Q)[w * 32 + lane];
    float4 acc = make_float4(0.f, 0.f, 0.f, 0.f);
    float ssum = 0.f;
    const uint2* kv = reinterpret_cast<const uint2*>(g_KVh);

    for (int i = beg; i < end; i += 4) {
        int s0 = g_esrc[i];
        int s1 = (i + 1 < end) ? g_esrc[i + 1] : -1;
        int s2 = (i + 2 < end) ? g_esrc[i + 2] : -1;
        int s3 = (i + 3 < end) ? g_esrc[i + 3] : -1;
        int a0 = s0, a1 = (s1 < 0) ? 0 : s1, a2 = (s2 < 0) ? 0 : s2, a3 = (s3 < 0) ? 0 : s3;
        // issue all 8 loads before compute (each 8B = 4 halves per lane)
        uint2 K0 = kv[a0 * 64 + lane];
        uint2 K1 = kv[a1 * 64 + lane];
        uint2 K2 = kv[a2 * 64 + lane];
        uint2 K3 = kv[a3 * 64 + lane];
        uint2 V0 = kv[a0 * 64 + 32 + lane];
        uint2 V1 = kv[a1 * 64 + 32 + lane];
        uint2 V2 = kv[a2 * 64 + 32 + lane];
        uint2 V3 = kv[a3 * 64 + 32 + lane];

        float2 k0a = __half22float2(*reinterpret_cast<__half2*>(&K0.x));
        float2 k0b = __half22float2(*reinterpret_cast<__half2*>(&K0.y));
        float2 k1a = __half22float2(*reinterpret_cast<__half2*>(&K1.x));
        float2 k1b = __half22float2(*reinterpret_cast<__half2*>(&K1.y));
        float2 k2a = __half22float2(*reinterpret_cast<__half2*>(&K2.x));
        float2 k2b = __half22float2(*reinterpret_cast<__half2*>(&K2.y));
        float2 k3a = __half22float2(*reinterpret_cast<__half2*>(&K3.x));
        float2 k3b = __half22float2(*reinterpret_cast<__half2*>(&K3.y));

        float p0 = k0a.x * q4.x + k0a.y * q4.y + k0b.x * q4.z + k0b.y * q4.w;
        float p1 = k1a.x * q4.x + k1a.y * q4.y + k1b.x * q4.z + k1b.y * q4.w;
        float p2 = k2a.x * q4.x + k2a.y * q4.y + k2b.x * q4.z + k2b.y * q4.w;
        float p3 = k3a.x * q4.x + k3a.y * q4.y + k3b.x * q4.z + k3b.y * q4.w;
        p0 += __shfl_xor_sync(0xffffffffu, p0, 1);
        p1 += __shfl_xor_sync(0xffffffffu, p1, 1);
        p2 += __shfl_xor_sync(0xffffffffu, p2, 1);
        p3 += __shfl_xor_sync(0xffffffffu, p3, 1);
        p0 += __shfl_xor_sync(0xffffffffu, p0, 2);
        p1 += __shfl_xor_sync(0xffffffffu, p1, 2);
        p2 += __shfl_xor_sync(0xffffffffu, p2, 2);
        p3 += __shfl_xor_sync(0xffffffffu, p3, 2);

        float w0 = __expf(fminf(fmaxf(p0 * 0.25f, -5.f), 5.f));
        float w1 = (s1 < 0) ? 0.f : __expf(fminf(fmaxf(p1 * 0.25f, -5.f), 5.f));
        float w2 = (s2 < 0) ? 0.f : __expf(fminf(fmaxf(p2 * 0.25f, -5.f), 5.f));
        float w3 = (s3 < 0) ? 0.f : __expf(fminf(fmaxf(p3 * 0.25f, -5.f), 5.f));

        float2 v0a = __half22float2(*reinterpret_cast<__half2*>(&V0.x));
        float2 v0b = __half22float2(*reinterpret_cast<__half2*>(&V0.y));
        float2 v1a = __half22float2(*reinterpret_cast<__half2*>(&V1.x));
        float2 v1b = __half22float2(*reinterpret_cast<__half2*>(&V1.y));
        float2 v2a = __half22float2(*reinterpret_cast<__half2*>(&V2.x));
        float2 v2b = __half22float2(*reinterpret_cast<__half2*>(&V2.y));
        float2 v3a = __half22float2(*reinterpret_cast<__half2*>(&V3.x));
        float2 v3b = __half22float2(*reinterpret_cast<__half2*>(&V3.y));

        ssum += (w0 + w1) + (w2 + w3);
        acc.x += w0 * v0a.x + w1 * v1a.x + w2 * v2a.x + w3 * v3a.x;
        acc.y += w0 * v0a.y + w1 * v1a.y + w2 * v2a.y + w3 * v3a.y;
        acc.z += w0 * v0b.x + w1 * v1b.x + w2 * v2b.x + w3 * v3b.x;
        acc.w += w0 * v0b.y + w1 * v1b.y + w2 * v2b.y + w3 * v3b.y;
    }
    float inv = 1.f / (ssum + 1e-16f);
    reinterpret_cast<float4*>(out)[w * 32 + lane] =
        make_float4(acc.x * inv, acc.y * inv, acc.z * inv, acc.w * inv);
}

// ---------------- launch ---------------------------------------------------
extern "C" void kernel_launch(void* const* d_in, const int* in_sizes, int n_in,
                              void* d_out, int out_size)
{
    const float* x   = (const float*)d_in[0];
    const float* ang = (const float*)d_in[1];
    const int*   ei  = (const int*)  d_in[2];
    const float* Wq  = (const float*)d_in[3];
    const float* bq  = (const float*)d_in[4];
    const float* Wk  = (const float*)d_in[5];
    const float* bk  = (const float*)d_in[6];
    const float* Wv  = (const float*)d_in[7];
    const float* bv  = (const float*)d_in[8];
    const float* S   = (const float*)d_in[9];
    float* out = (float*)d_out;

    int N = in_sizes[0] / 128;
    int E = in_sizes[2] / 2;

    cudaFuncSetAttribute(qkv_mma_kernel,
                         cudaFuncAttributeMaxDynamicSharedMemorySize, QKV_SMEM);

    softmaxS_kernel<<<1, 256>>>(S);
    wconv_kernel<<<(3 * 16384 + 255) / 256, 256>>>(Wq, Wk, Wv);

    zero_cnt_kernel<<<(N + 256) / 256, 256>>>(N);
    hist_kernel<<<(E + 255) / 256, 256>>>(ei, E);
    scan_kernel<<<1, 1024>>>(N);
    scatter_kernel<<<(E + 255) / 256, 256>>>(ei, E);

    qkv_mma_kernel<<<(N + 63) / 64, 256, QKV_SMEM>>>(x, ang, bq, bk, bv, N);

    agg_kernel<<<(N + 7) / 8, 256>>>(out, N);
}

// round 9
// speedup vs baseline: 2.3173x; 1.3515x over previous
#include <cuda_runtime.h>
#include <cuda_bf16.h>
#include <cuda_fp16.h>
#include <cstdint>

#define N_NODES 50000
#define MAX_E   800000

// ---------------- device scratch ------------------------------------------
__device__ float g_Q[N_NODES * 128];
__device__ __half g_KVh[N_NODES * 256];            // [node][K:128 | V:128] fp16
__device__ float g_P[256];                         // softmax(S): [4][64]
// W packed in mma b-frag order: [ph][kt:8][nt:16][lane:32][8 bf16: hi w0b0,w0b1,w1b0,w1b1, lo ...]
__device__ __nv_bfloat16 g_Wf[3 * 8 * 16 * 32 * 8];
// CSR scratch
__device__ int g_cnt[N_NODES + 1];
__device__ int g_off[N_NODES + 1];
__device__ int g_pos[N_NODES + 1];
__device__ int g_esrc[MAX_E];

// ---------------- helpers --------------------------------------------------
__device__ __forceinline__ uint32_t smem_u32(const void* p) {
    uint32_t a;
    asm("{ .reg .u64 t; cvta.to.shared.u64 t, %1; cvt.u32.u64 %0, t; }" : "=r"(a) : "l"(p));
    return a;
}
__device__ __forceinline__ void ldm_x4(uint32_t* r, uint32_t addr) {
    asm volatile("ldmatrix.sync.aligned.m8n8.x4.shared.b16 {%0,%1,%2,%3}, [%4];"
                 : "=r"(r[0]), "=r"(r[1]), "=r"(r[2]), "=r"(r[3]) : "r"(addr));
}
__device__ __forceinline__ void mma16816(float* d, const uint32_t* a, uint32_t b0, uint32_t b1) {
    asm volatile("mma.sync.aligned.m16n8k16.row.col.f32.bf16.bf16.f32 "
                 "{%0,%1,%2,%3}, {%4,%5,%6,%7}, {%8,%9}, {%0,%1,%2,%3};"
                 : "+f"(d[0]), "+f"(d[1]), "+f"(d[2]), "+f"(d[3])
                 : "r"(a[0]), "r"(a[1]), "r"(a[2]), "r"(a[3]), "r"(b0), "r"(b1));
}
__device__ __forceinline__ uint32_t pack_bf2(__nv_bfloat16 a, __nv_bfloat16 b) {
    return (uint32_t)__bfloat16_as_ushort(a) | ((uint32_t)__bfloat16_as_ushort(b) << 16);
}

// smem layout (bytes). x tiles: 64 rows x 136 bf16 (pitch 272B)
#define XH_OFF  0
#define XL_OFF  17408
#define OUT_OFF 34816                 // 64 x 132 f32
#define QKV_SMEM (34816 + 64 * 132 * 4)   // 68608

// ---------------- P = softmax(S, axis=1), S: [4][64] ----------------------
__global__ void softmaxS_kernel(const float* __restrict__ S) {
    int t = threadIdx.x;
    int a = t >> 6, c = t & 63;
    float v = __expf(S[a * 64 + c]);
    float s = v;
    #pragma unroll
    for (int o = 16; o; o >>= 1) s += __shfl_xor_sync(0xffffffffu, s, o);
    __shared__ float part[8];
    if ((t & 31) == 0) part[t >> 5] = s;
    __syncthreads();
    float sum = part[a * 2] + part[a * 2 + 1];
    g_P[a * 64 + c] = v / sum;
}

// ---------------- W[k][n] -> packed mma b-frags (bf16 hi/lo) --------------
__global__ void wconv_kernel(const float* __restrict__ Wq,
                             const float* __restrict__ Wk,
                             const float* __restrict__ Wv) {
    int i = blockIdx.x * blockDim.x + threadIdx.x;
    if (i >= 3 * 16384) return;
    int ph = i >> 14, rem = i & 16383;
    int k = rem >> 7, n = rem & 127;                 // coalesced read in n
    const float* W = (ph == 0) ? Wq : (ph == 1) ? Wk : Wv;
    float v = W[k * 128 + n];
    __nv_bfloat16 hi = __float2bfloat16_rn(v);
    __nv_bfloat16 lo = __float2bfloat16_rn(v - __bfloat162float(hi));
    int kt = k >> 4, nt = n >> 3;
    int t  = ((n & 7) << 2) | ((k & 7) >> 1);
    int word = (k >> 3) & 1, half = k & 1;
    size_t base = ((size_t)((ph * 8 + kt) * 16 + nt) * 32 + t) * 8;
    g_Wf[base + word * 2 + half]     = hi;
    g_Wf[base + 4 + word * 2 + half] = lo;
}

// ---------------- fused QKV GEMM (mma.sync bf16 split) + bias + RoPE ------
__global__ __launch_bounds__(256, 2) void qkv_mma_kernel(
    const float* __restrict__ x, const float* __restrict__ ang,
    const float* __restrict__ bq, const float* __restrict__ bk,
    const float* __restrict__ bv, int N)
{
    extern __shared__ char smem[];
    uint32_t sb = smem_u32(smem);
    int tid = threadIdx.x, wid = tid >> 5, lane = tid & 31;
    int row0 = blockIdx.x * 64;

    #pragma unroll
    for (int j = 0; j < 8; ++j) {
        int idx  = tid + 256 * j;
        int row  = idx >> 5;
        int col0 = (idx & 31) * 4;
        int gr   = row0 + row;
        float4 v = make_float4(0.f, 0.f, 0.f, 0.f);
        if (gr < N) v = *reinterpret_cast<const float4*>(&x[(size_t)gr * 128 + col0]);
        __nv_bfloat16 h0 = __float2bfloat16_rn(v.x), h1 = __float2bfloat16_rn(v.y);
        __nv_bfloat16 h2 = __float2bfloat16_rn(v.z), h3 = __float2bfloat16_rn(v.w);
        __nv_bfloat16 l0 = __float2bfloat16_rn(v.x - __bfloat162float(h0));
        __nv_bfloat16 l1 = __float2bfloat16_rn(v.y - __bfloat162float(h1));
        __nv_bfloat16 l2 = __float2bfloat16_rn(v.z - __bfloat162float(h2));
        __nv_bfloat16 l3 = __float2bfloat16_rn(v.w - __bfloat162float(h3));
        uint32_t off = (uint32_t)row * 272u + (uint32_t)col0 * 2u;
        *reinterpret_cast<uint2*>(smem + XH_OFF + off) = make_uint2(pack_bf2(h0, h1), pack_bf2(h2, h3));
        *reinterpret_cast<uint2*>(smem + XL_OFF + off) = make_uint2(pack_bf2(l0, l1), pack_bf2(l2, l3));
    }
    __syncthreads();

    int wm = wid & 3;
    int wn = wid >> 2;
    float* outs = reinterpret_cast<float*>(smem + OUT_OFF);

    for (int ph = 0; ph < 3; ++ph) {
        float d[8][4];
        #pragma unroll
        for (int nj = 0; nj < 8; ++nj)
            #pragma unroll
            for (int q = 0; q < 4; ++q) d[nj][q] = 0.f;

        const uint4* wf = reinterpret_cast<const uint4*>(g_Wf) + ((size_t)ph * 8 * 16 + wn * 8) * 32 + lane;

        #pragma unroll 2
        for (int kk = 0; kk < 8; ++kk) {
            uint32_t ah[4], al[4];
            {
                int r = wm * 16 + (lane & 15);
                int c = kk * 16 + (lane >> 4) * 8;
                uint32_t a = sb + XH_OFF + (uint32_t)r * 272u + (uint32_t)c * 2u;
                ldm_x4(ah, a);
                ldm_x4(al, a + (XL_OFF - XH_OFF));
            }
            uint4 bfr[8];
            #pragma unroll
            for (int nj = 0; nj < 8; ++nj)
                bfr[nj] = wf[((size_t)kk * 16 + nj) * 32];
            #pragma unroll
            for (int nj = 0; nj < 8; ++nj) {
                mma16816(d[nj], ah, bfr[nj].x, bfr[nj].y);
                mma16816(d[nj], ah, bfr[nj].z, bfr[nj].w);
                mma16816(d[nj], al, bfr[nj].x, bfr[nj].y);
            }
        }

        #pragma unroll
        for (int nj = 0; nj < 8; ++nj) {
            int r = wm * 16 + (lane >> 2);
            int c = wn * 64 + nj * 8 + 2 * (lane & 3);
            *reinterpret_cast<float2*>(&outs[r * 132 + c])       = make_float2(d[nj][0], d[nj][1]);
            *reinterpret_cast<float2*>(&outs[(r + 8) * 132 + c]) = make_float2(d[nj][2], d[nj][3]);
        }
        __syncthreads();

        {
            const float* bias = (ph == 0) ? bq : (ph == 1) ? bk : bv;
            #pragma unroll
            for (int rr = 0; rr < 8; ++rr) {
                int row = wid * 8 + rr;
                int n = row0 + row;
                if (n >= N) break;
                int j0 = lane * 4;
                const float* orow = &outs[row * 132];
                float v0 = orow[j0 + 0] + bias[j0 + 0];
                float v1 = orow[j0 + 1] + bias[j0 + 1];
                float v2 = orow[j0 + 2] + bias[j0 + 2];
                float v3 = orow[j0 + 3] + bias[j0 + 3];
                float4 ov;
                if (ph < 2) {
                    float a0 = ang[n * 4 + 0], a1 = ang[n * 4 + 1];
                    float a2 = ang[n * 4 + 2], a3 = ang[n * 4 + 3];
                    int m0 = 2 * lane, m1 = 2 * lane + 1;
                    float t0 = a0 * g_P[m0] + a1 * g_P[64 + m0] + a2 * g_P[128 + m0] + a3 * g_P[192 + m0];
                    float t1 = a0 * g_P[m1] + a1 * g_P[64 + m1] + a2 * g_P[128 + m1] + a3 * g_P[192 + m1];
                    float c0, s0, c1, s1;
                    __sincosf(t0, &s0, &c0);
                    __sincosf(t1, &s1, &c1);
                    float pv[4];
                    #pragma unroll
                    for (int i = 0; i < 4; ++i) {
                        int j = j0 + i;
                        int jj = j & 15, hb = j & 0x70;
                        int p; float sg;
                        if (jj < 8) { p = hb + 2 * jj + 1;  sg = -1.f; }
                        else        { p = hb + 2 * jj - 16; sg =  1.f; }
                        pv[i] = sg * (orow[p] + bias[p]);
                    }
                    ov.x = v0 * c0 + pv[0] * s0;
                    ov.y = v1 * c0 + pv[1] * s0;
                    ov.z = v2 * c1 + pv[2] * s1;
                    ov.w = v3 * c1 + pv[3] * s1;
                } else {
                    ov = make_float4(v0, v1, v2, v3);
                }
                if (ph == 0) {
                    *reinterpret_cast<float4*>(&g_Q[(size_t)n * 128 + j0]) = ov;
                } else {
                    __half2 h01 = __floats2half2_rn(ov.x, ov.y);
                    __half2 h23 = __floats2half2_rn(ov.z, ov.w);
                    uint2 pk = make_uint2(*reinterpret_cast<uint32_t*>(&h01),
                                          *reinterpret_cast<uint32_t*>(&h23));
                    size_t gi = (size_t)n * 256 + (ph == 1 ? 0 : 128) + j0;
                    *reinterpret_cast<uint2*>(&g_KVh[gi]) = pk;
                }
            }
        }
        __syncthreads();
    }
}

// ---------------- CSR build: zero counts, histogram, scan, scatter --------
__global__ void zero_cnt_kernel(int N) {
    int i = blockIdx.x * blockDim.x + threadIdx.x;
    if (i <= N) g_cnt[i] = 0;
}
__global__ void hist_kernel(const int* __restrict__ ei, int E) {
    int e = blockIdx.x * blockDim.x + threadIdx.x;
    if (e < E) atomicAdd(&g_cnt[ei[E + e]], 1);
}
__global__ __launch_bounds__(1024) void scan_kernel(int N) {
    __shared__ int sums[1024];
    int t = threadIdx.x;
    int chunk = (N + 1023) / 1024;
    int lo = t * chunk, hi = min(lo + chunk, N);
    int s = 0;
    for (int i = lo; i < hi; ++i) s += g_cnt[i];
    sums[t] = s;
    __syncthreads();
    #pragma unroll
    for (int off = 1; off < 1024; off <<= 1) {
        int v = (t >= off) ? sums[t - off] : 0;
        __syncthreads();
        sums[t] += v;
        __syncthreads();
    }
    int base = sums[t] - s;
    for (int i = lo; i < hi; ++i) {
        g_off[i] = base;
        g_pos[i] = base;
        base += g_cnt[i];
    }
    if (t == 1023) g_off[N] = sums[1023];
}
__global__ void scatter_kernel(const int* __restrict__ ei, int E) {
    int e = blockIdx.x * blockDim.x + threadIdx.x;
    if (e >= E) return;
    int src = ei[e];
    int dst = ei[E + e];
    int p = atomicAdd(&g_pos[dst], 1);
    g_esrc[p] = src;
}

// ---------------- aggregation: warp per dst node, fp16 K/V ----------------
__global__ __launch_bounds__(256) void agg_kernel(float* __restrict__ out, int N) {
    int w    = (blockIdx.x * blockDim.x + threadIdx.x) >> 5;
    int lane = threadIdx.x & 31;
    if (w >= N) return;
    int beg = g_off[w], end = g_off[w + 1];

    float4 q4 = reinterpret_cast<const float4*>(g_Q)[w * 32 + lane];
    float4 acc = make_float4(0.f, 0.f, 0.f, 0.f);
    float ssum = 0.f;
    const uint2* kv = reinterpret_cast<const uint2*>(g_KVh);

    for (int i = beg; i < end; i += 4) {
        int s0 = g_esrc[i];
        int s1 = (i + 1 < end) ? g_esrc[i + 1] : -1;
        int s2 = (i + 2 < end) ? g_esrc[i + 2] : -1;
        int s3 = (i + 3 < end) ? g_esrc[i + 3] : -1;
        int a0 = s0, a1 = (s1 < 0) ? 0 : s1, a2 = (s2 < 0) ? 0 : s2, a3 = (s3 < 0) ? 0 : s3;
        uint2 K0 = kv[a0 * 64 + lane];
        uint2 K1 = kv[a1 * 64 + lane];
        uint2 K2 = kv[a2 * 64 + lane];
        uint2 K3 = kv[a3 * 64 + lane];
        uint2 V0 = kv[a0 * 64 + 32 + lane];
        uint2 V1 = kv[a1 * 64 + 32 + lane];
        uint2 V2 = kv[a2 * 64 + 32 + lane];
        uint2 V3 = kv[a3 * 64 + 32 + lane];

        float2 k0a = __half22float2(*reinterpret_cast<__half2*>(&K0.x));
        float2 k0b = __half22float2(*reinterpret_cast<__half2*>(&K0.y));
        float2 k1a = __half22float2(*reinterpret_cast<__half2*>(&K1.x));
        float2 k1b = __half22float2(*reinterpret_cast<__half2*>(&K1.y));
        float2 k2a = __half22float2(*reinterpret_cast<__half2*>(&K2.x));
        float2 k2b = __half22float2(*reinterpret_cast<__half2*>(&K2.y));
        float2 k3a = __half22float2(*reinterpret_cast<__half2*>(&K3.x));
        float2 k3b = __half22float2(*reinterpret_cast<__half2*>(&K3.y));

        float p0 = k0a.x * q4.x + k0a.y * q4.y + k0b.x * q4.z + k0b.y * q4.w;
        float p1 = k1a.x * q4.x + k1a.y * q4.y + k1b.x * q4.z + k1b.y * q4.w;
        float p2 = k2a.x * q4.x + k2a.y * q4.y + k2b.x * q4.z + k2b.y * q4.w;
        float p3 = k3a.x * q4.x + k3a.y * q4.y + k3b.x * q4.z + k3b.y * q4.w;
        p0 += __shfl_xor_sync(0xffffffffu, p0, 1);
        p1 += __shfl_xor_sync(0xffffffffu, p1, 1);
        p2 += __shfl_xor_sync(0xffffffffu, p2, 1);
        p3 += __shfl_xor_sync(0xffffffffu, p3, 1);
        p0 += __shfl_xor_sync(0xffffffffu, p0, 2);
        p1 += __shfl_xor_sync(0xffffffffu, p1, 2);
        p2 += __shfl_xor_sync(0xffffffffu, p2, 2);
        p3 += __shfl_xor_sync(0xffffffffu, p3, 2);

        float w0 = __expf(fminf(fmaxf(p0 * 0.25f, -5.f), 5.f));
        float w1 = (s1 < 0) ? 0.f : __expf(fminf(fmaxf(p1 * 0.25f, -5.f), 5.f));
        float w2 = (s2 < 0) ? 0.f : __expf(fminf(fmaxf(p2 * 0.25f, -5.f), 5.f));
        float w3 = (s3 < 0) ? 0.f : __expf(fminf(fmaxf(p3 * 0.25f, -5.f), 5.f));

        float2 v0a = __half22float2(*reinterpret_cast<__half2*>(&V0.x));
        float2 v0b = __half22float2(*reinterpret_cast<__half2*>(&V0.y));
        float2 v1a = __half22float2(*reinterpret_cast<__half2*>(&V1.x));
        float2 v1b = __half22float2(*reinterpret_cast<__half2*>(&V1.y));
        float2 v2a = __half22float2(*reinterpret_cast<__half2*>(&V2.x));
        float2 v2b = __half22float2(*reinterpret_cast<__half2*>(&V2.y));
        float2 v3a = __half22float2(*reinterpret_cast<__half2*>(&V3.x));
        float2 v3b = __half22float2(*reinterpret_cast<__half2*>(&V3.y));

        ssum += (w0 + w1) + (w2 + w3);
        acc.x += w0 * v0a.x + w1 * v1a.x + w2 * v2a.x + w3 * v3a.x;
        acc.y += w0 * v0a.y + w1 * v1a.y + w2 * v2a.y + w3 * v3a.y;
        acc.z += w0 * v0b.x + w1 * v1b.x + w2 * v2b.x + w3 * v3b.x;
        acc.w += w0 * v0b.y + w1 * v1b.y + w2 * v2b.y + w3 * v3b.y;
    }
    float inv = 1.f / (ssum + 1e-16f);
    reinterpret_cast<float4*>(out)[w * 32 + lane] =
        make_float4(acc.x * inv, acc.y * inv, acc.z * inv, acc.w * inv);
}

// ---------------- launch: two-stream overlap (CSR prep || QKV GEMM) -------
extern "C" void kernel_launch(void* const* d_in, const int* in_sizes, int n_in,
                              void* d_out, int out_size)
{
    const float* x   = (const float*)d_in[0];
    const float* ang = (const float*)d_in[1];
    const int*   ei  = (const int*)  d_in[2];
    const float* Wq  = (const float*)d_in[3];
    const float* bq  = (const float*)d_in[4];
    const float* Wk  = (const float*)d_in[5];
    const float* bk  = (const float*)d_in[6];
    const float* Wv  = (const float*)d_in[7];
    const float* bv  = (const float*)d_in[8];
    const float* S   = (const float*)d_in[9];
    float* out = (float*)d_out;

    int N = in_sizes[0] / 128;
    int E = in_sizes[2] / 2;

    // one-time host-side setup (no device memory allocation)
    static cudaStream_t s2 = nullptr;
    static cudaEvent_t evFork = nullptr, evJoin = nullptr;
    static bool attr_done = false;
    if (!attr_done) {
        cudaFuncSetAttribute(qkv_mma_kernel,
                             cudaFuncAttributeMaxDynamicSharedMemorySize, QKV_SMEM);
        cudaStreamCreateWithFlags(&s2, cudaStreamNonBlocking);
        cudaEventCreateWithFlags(&evFork, cudaEventDisableTiming);
        cudaEventCreateWithFlags(&evJoin, cudaEventDisableTiming);
        attr_done = true;
    }

    // fork side stream off the (possibly capturing) default stream
    cudaEventRecord(evFork, 0);
    cudaStreamWaitEvent(s2, evFork, 0);

    // side stream: CSR build (independent of GEMM path)
    zero_cnt_kernel<<<(N + 256) / 256, 256, 0, s2>>>(N);
    hist_kernel<<<(E + 255) / 256, 256, 0, s2>>>(ei, E);
    scan_kernel<<<1, 1024, 0, s2>>>(N);
    scatter_kernel<<<(E + 255) / 256, 256, 0, s2>>>(ei, E);
    cudaEventRecord(evJoin, s2);

    // main stream: projection path
    softmaxS_kernel<<<1, 256>>>(S);
    wconv_kernel<<<(3 * 16384 + 255) / 256, 256>>>(Wq, Wk, Wv);
    qkv_mma_kernel<<<(N + 63) / 64, 256, QKV_SMEM>>>(x, ang, bq, bk, bv, N);

    // join, then aggregate
    cudaStreamWaitEvent(0, evJoin, 0);
    agg_kernel<<<(N + 7) / 8, 256>>>(out, N);
}